// round 14
// baseline (speedup 1.0000x reference)
#include <cuda_runtime.h>
#include <cstdint>

#define B_    4
#define N_    2048
#define DIM_  384
#define H_    8
#define HD_   48
#define HID_  1024
#define M_    (B_*N_)          // 8192
#define SCALE_ 0.14433756729740643f   // 48^-0.5
#define EPS_   1e-5f

// ---------------- scratch (no allocation allowed; __device__ globals) ----------
__device__ float g_xa [M_*DIM_];
__device__ float g_Q  [M_*DIM_];   // [B,H,N,HD]
__device__ float g_K  [M_*DIM_];
__device__ float g_V  [M_*DIM_];
__device__ float g_O  [M_*DIM_];   // [B,N,H*HD]
__device__ float g_h  [M_*DIM_];
__device__ float g_hf [M_*DIM_];
__device__ float g_gb [M_*HID_];

__device__ __forceinline__ void mma_tf32(float c[4], const uint32_t a[4], const uint32_t b[2]) {
    asm volatile(
        "mma.sync.aligned.m16n8k8.row.col.f32.tf32.tf32.f32 "
        "{%0,%1,%2,%3}, {%4,%5,%6,%7}, {%8,%9}, {%0,%1,%2,%3};"
        : "+f"(c[0]), "+f"(c[1]), "+f"(c[2]), "+f"(c[3])
        : "r"(a[0]), "r"(a[1]), "r"(a[2]), "r"(a[3]),
          "r"(b[0]), "r"(b[1]));
}

__device__ __forceinline__ uint32_t smem_u32(const void* p) {
    return (uint32_t)__cvta_generic_to_shared(p);
}
__device__ __forceinline__ void cp16(uint32_t dst, const void* src) {
    asm volatile("cp.async.cg.shared.global [%0], [%1], 16;" :: "r"(dst), "l"(src));
}
#define CP_COMMIT()  asm volatile("cp.async.commit_group;")
#define CP_WAIT(n)   asm volatile("cp.async.wait_group %0;" :: "n"(n))

// ---------------- RMSNorm: one row (384) per block of 128 threads --------------
__global__ void rmsnorm_kernel(const float* __restrict__ src,
                               const float* __restrict__ w,
                               float* __restrict__ dst) {
    const int row = blockIdx.x;
    const int tid = threadIdx.x;
    const float* xr = src + row*DIM_;
    float v0 = xr[tid], v1 = xr[tid+128], v2 = xr[tid+256];
    float s = v0*v0 + v1*v1 + v2*v2;
    #pragma unroll
    for (int o = 16; o > 0; o >>= 1) s += __shfl_xor_sync(0xffffffffu, s, o);
    __shared__ float red[4];
    if ((tid & 31) == 0) red[tid >> 5] = s;
    __syncthreads();
    float tot = red[0] + red[1] + red[2] + red[3];
    float sc = rsqrtf(tot * (1.0f/DIM_) + EPS_);
    float* dr = dst + row*DIM_;
    dr[tid]     = v0*sc*w[tid];
    dr[tid+128] = v1*sc*w[tid+128];
    dr[tid+256] = v2*sc*w[tid+256];
}

// ---------------- 64x64-tile tf32 GEMM, BK=32, 256 thr (8 warps) ---------------
// warp tile 16x32 (4M x 2N warp grid); 3-stage cp.async; stride 36 smem.
#define MODE_QKV   1
#define MODE_PROJ  2
#define MODE_FINAL 5

#define SSTR 36
#define TSTG_W (64*SSTR)                       // 2304 words per matrix per stage
#define GEMM_SMEM_BYTES (2 * 3 * TSTG_W * 4)   // 55296
#define GLU_SMEM_BYTES  (3 * 2 * TSTG_W * 4)   // 55296

template<int KDIM, int MODE>
__global__ void __launch_bounds__(256, 3) gemm_tc_kernel(
    const float* __restrict__ A, const float* __restrict__ W,
    float* __restrict__ C,
    const float* __restrict__ aux1,   // pos | b_proj | -
    const float* __restrict__ aux2,   // -   | x      | h
    const int* __restrict__ npts)
{
    extern __shared__ float dsm[];
    float* As = dsm;                  // [3][TSTG_W]
    float* Bs = dsm + 3*TSTG_W;       // [3][TSTG_W]

    const int tid  = threadIdx.x;
    const int bm   = blockIdx.y << 6;
    const int bn   = blockIdx.x << 6;
    const int warp = tid >> 5;
    const int wm   = (warp & 3) * 16;      // 4 M-slabs
    const int wn   = (warp >> 2) * 32;     // 2 N-slabs
    const int lane = tid & 31;
    const int gid  = lane >> 2;
    const int tg   = lane & 3;

    const int r0 = tid >> 3;          // 0..31
    const int c0 = (tid & 7) << 2;    // 0,4,...,28

    float acc[4][4];
    #pragma unroll
    for (int nt = 0; nt < 4; nt++)
        #pragma unroll
        for (int e = 0; e < 4; e++) acc[nt][e] = 0.f;

    const float* Ap = A + (long long)(bm + r0)*KDIM + c0;
    const float* Wp = W + (long long)(bn + r0)*KDIM + c0;
    const uint32_t dA = smem_u32(&As[r0*SSTR + c0]);
    const uint32_t dB = smem_u32(&Bs[r0*SSTR + c0]);
    const uint32_t half_off = (uint32_t)(32*SSTR)*4;

    auto load_stage = [&](int sbuf, int k0) {
        const uint32_t ob = (uint32_t)(sbuf * TSTG_W * 4);
        cp16(dA + ob,            Ap + k0);
        cp16(dA + ob + half_off, Ap + (long long)32*KDIM + k0);
        cp16(dB + ob,            Wp + k0);
        cp16(dB + ob + half_off, Wp + (long long)32*KDIM + k0);
    };

    constexpr int NK = KDIM / 32;
    load_stage(0, 0);  CP_COMMIT();
    load_stage(1, 32); CP_COMMIT();

    int sb = 0;
    for (int kt = 0; kt < NK; kt++) {
        CP_WAIT(1);
        __syncthreads();
        if (kt + 2 < NK) {
            int nb = sb + 2; if (nb >= 3) nb -= 3;
            load_stage(nb, (kt + 2) * 32);
        }
        CP_COMMIT();

        const float* Ab = As + sb*TSTG_W;
        const float* Bb = Bs + sb*TSTG_W;
        #pragma unroll
        for (int ks = 0; ks < 4; ks++) {
            const int kb = ks << 3;
            uint32_t af[4];
            uint32_t bf[4][2];
            af[0] = __float_as_uint(Ab[(wm+gid  )*SSTR + kb+tg]);
            af[1] = __float_as_uint(Ab[(wm+gid+8)*SSTR + kb+tg]);
            af[2] = __float_as_uint(Ab[(wm+gid  )*SSTR + kb+tg+4]);
            af[3] = __float_as_uint(Ab[(wm+gid+8)*SSTR + kb+tg+4]);
            #pragma unroll
            for (int nt = 0; nt < 4; nt++) {
                const int n0 = wn + nt*8;
                bf[nt][0] = __float_as_uint(Bb[(n0+gid)*SSTR + kb+tg]);
                bf[nt][1] = __float_as_uint(Bb[(n0+gid)*SSTR + kb+tg+4]);
            }
            #pragma unroll
            for (int nt = 0; nt < 4; nt++)
                mma_tf32(acc[nt], af, bf[nt]);
        }
        if (++sb == 3) sb = 0;
    }

    #pragma unroll
    for (int nt = 0; nt < 4; nt++) {
        #pragma unroll
        for (int e = 0; e < 4; e++) {
            const int m = bm + wm + gid + ((e & 2) ? 8 : 0);
            const int n = bn + wn + nt*8 + tg*2 + (e & 1);
            float v = acc[nt][e];
            if constexpr (MODE == MODE_QKV) {
                const int b    = m >> 11;
                const int ns   = m & 2047;
                const int part = n / DIM_;
                const int rem  = n - part*DIM_;
                const int hh   = rem / HD_;
                const int hd   = rem - hh*HD_;
                if (part < 2) v += aux1[(b*N_ + ns)*HD_ + hd];
                float* dst = (part == 0) ? g_Q : (part == 1 ? g_K : g_V);
                dst[(((b << 3) + hh)*N_ + ns)*HD_ + hd] = v;
            } else if constexpr (MODE == MODE_PROJ) {
                C[m*DIM_ + n] = v + aux1[n] + aux2[m*DIM_ + n];
            } else if constexpr (MODE == MODE_FINAL) {
                const int np = npts[m >> 11];
                C[m*DIM_ + n] = ((m & 2047) < np)
                                ? (aux2[m*DIM_ + n] + v) : 0.0f;
            }
        }
    }
}

// ---------------- fused GLU GEMM (64x64, BK=32, 2 stages, 256 thr) -------------
__global__ void __launch_bounds__(256, 3) gemm_glu_kernel(
    const float* __restrict__ A, const float* __restrict__ W1,
    const float* __restrict__ W3, float* __restrict__ C)
{
    extern __shared__ float gsm[];
    float* As = gsm;                   // [2][TSTG_W]
    float* B1 = gsm + 2*TSTG_W;
    float* B3 = gsm + 4*TSTG_W;

    const int tid  = threadIdx.x;
    const int bm   = blockIdx.y << 6;
    const int bn   = blockIdx.x << 6;
    const int warp = tid >> 5;
    const int wm   = (warp & 3) * 16;
    const int wn   = (warp >> 2) * 32;
    const int lane = tid & 31;
    const int gid  = lane >> 2;
    const int tg   = lane & 3;
    const int r0   = tid >> 3;
    const int c0   = (tid & 7) << 2;

    float acc1[4][4], acc3[4][4];
    #pragma unroll
    for (int nt = 0; nt < 4; nt++)
        #pragma unroll
        for (int e = 0; e < 4; e++) { acc1[nt][e] = 0.f; acc3[nt][e] = 0.f; }

    const float* Ap  = A  + (long long)(bm + r0)*DIM_ + c0;
    const float* W1p = W1 + (long long)(bn + r0)*DIM_ + c0;
    const float* W3p = W3 + (long long)(bn + r0)*DIM_ + c0;
    const uint32_t dA = smem_u32(&As[r0*SSTR + c0]);
    const uint32_t d1 = smem_u32(&B1[r0*SSTR + c0]);
    const uint32_t d3 = smem_u32(&B3[r0*SSTR + c0]);
    const uint32_t half_off = (uint32_t)(32*SSTR)*4;

    auto load_stage = [&](int sbuf, int k0) {
        const uint32_t ob = (uint32_t)(sbuf * TSTG_W * 4);
        cp16(dA + ob,            Ap  + k0);
        cp16(dA + ob + half_off, Ap  + (long long)32*DIM_ + k0);
        cp16(d1 + ob,            W1p + k0);
        cp16(d1 + ob + half_off, W1p + (long long)32*DIM_ + k0);
        cp16(d3 + ob,            W3p + k0);
        cp16(d3 + ob + half_off, W3p + (long long)32*DIM_ + k0);
    };

    constexpr int NK = DIM_ / 32;      // 12
    load_stage(0, 0);
    CP_COMMIT();

    int buf = 0;
    for (int kt = 0; kt < NK; kt++) {
        if (kt + 1 < NK) {
            load_stage(buf ^ 1, (kt + 1) * 32);
            CP_COMMIT();
            CP_WAIT(1);
        } else {
            CP_WAIT(0);
        }
        __syncthreads();

        const float* Ab  = As + buf*TSTG_W;
        const float* B1b = B1 + buf*TSTG_W;
        const float* B3b = B3 + buf*TSTG_W;
        #pragma unroll
        for (int ks = 0; ks < 4; ks++) {
            const int kb = ks << 3;
            uint32_t af[4];
            af[0] = __float_as_uint(Ab[(wm+gid  )*SSTR + kb+tg]);
            af[1] = __float_as_uint(Ab[(wm+gid+8)*SSTR + kb+tg]);
            af[2] = __float_as_uint(Ab[(wm+gid  )*SSTR + kb+tg+4]);
            af[3] = __float_as_uint(Ab[(wm+gid+8)*SSTR + kb+tg+4]);
            #pragma unroll
            for (int nt = 0; nt < 4; nt++) {
                const int n0 = wn + nt*8;
                uint32_t b1f[2], b3f[2];
                b1f[0] = __float_as_uint(B1b[(n0+gid)*SSTR + kb+tg]);
                b1f[1] = __float_as_uint(B1b[(n0+gid)*SSTR + kb+tg+4]);
                b3f[0] = __float_as_uint(B3b[(n0+gid)*SSTR + kb+tg]);
                b3f[1] = __float_as_uint(B3b[(n0+gid)*SSTR + kb+tg+4]);
                mma_tf32(acc1[nt], af, b1f);
                mma_tf32(acc3[nt], af, b3f);
            }
        }
        __syncthreads();
        buf ^= 1;
    }

    #pragma unroll
    for (int nt = 0; nt < 4; nt++) {
        #pragma unroll
        for (int e = 0; e < 4; e++) {
            const int m = bm + wm + gid + ((e & 2) ? 8 : 0);
            const int n = bn + wn + nt*8 + tg*2 + (e & 1);
            const float v1 = acc1[nt][e];
            const float v3 = acc3[nt][e];
            C[m*HID_ + n] = (v1 / (1.0f + __expf(-v1))) * v3;
        }
    }
}

// ---------------- pipelined tensor-core flash attention (unchanged R8) ---------
#define AT_KSTR 52
#define AT_VSTR 56
#define AT_PSTR 68
#define AT_PSQ_W (64*AT_PSTR)
#define AT_K_W   (64*AT_KSTR)
#define AT_V_W   (64*AT_VSTR)
#define AT_SMEM_BYTES ((AT_PSQ_W + 2*AT_K_W + 2*AT_V_W) * 4)

__global__ void __launch_bounds__(128, 3) attn_tc_kernel(const float* __restrict__ mask) {
    extern __shared__ float sm[];
    float* PsQ = sm;
    float* Kd  = sm + AT_PSQ_W;
    float* Vd  = Kd + 2*AT_K_W;

    const int bh  = blockIdx.y;
    const int b   = bh >> 3;
    const int hh  = bh & 7;
    const int q0  = blockIdx.x * 64;
    const int tid = threadIdx.x;
    const int warp = tid >> 5;
    const int lane = tid & 31;
    const int gid  = lane >> 2;
    const int tg   = lane & 3;
    const int m0   = warp * 16;

    const float* Qbase = g_Q + ((long long)bh*N_ + q0)*HD_;
    const uint32_t qdst = smem_u32(PsQ);
    for (int i = tid; i < 64*12; i += 128) {
        const int row = i / 12, c = i - row*12;
        cp16(qdst + (uint32_t)(row*AT_KSTR + c*4)*4, Qbase + row*HD_ + c*4);
    }
    CP_COMMIT();

    const float* Kbase = g_K + (long long)bh*N_*HD_;
    const float* Vbase = g_V + (long long)bh*N_*HD_;
    const uint32_t kdst = smem_u32(Kd);
    const uint32_t vdst = smem_u32(Vd);

    auto load_tile = [&](int bufi, int k0) {
        const uint32_t kb = kdst + (uint32_t)(bufi*AT_K_W)*4;
        const uint32_t vb = vdst + (uint32_t)(bufi*AT_V_W)*4;
        for (int i = tid; i < 64*12; i += 128) {
            const int row = i / 12, c = i - row*12;
            cp16(kb + (uint32_t)(row*AT_KSTR + c*4)*4, Kbase + (k0+row)*HD_ + c*4);
            cp16(vb + (uint32_t)(row*AT_VSTR + c*4)*4, Vbase + (k0+row)*HD_ + c*4);
        }
    };

    load_tile(0, 0);
    CP_COMMIT();

    CP_WAIT(1);
    __syncthreads();
    uint32_t qf[6][4];
    #pragma unroll
    for (int ks = 0; ks < 6; ks++) {
        const int kb = ks*8;
        qf[ks][0] = __float_as_uint(PsQ[(m0+gid  )*AT_KSTR + kb+tg]);
        qf[ks][1] = __float_as_uint(PsQ[(m0+gid+8)*AT_KSTR + kb+tg]);
        qf[ks][2] = __float_as_uint(PsQ[(m0+gid  )*AT_KSTR + kb+tg+4]);
        qf[ks][3] = __float_as_uint(PsQ[(m0+gid+8)*AT_KSTR + kb+tg+4]);
    }
    __syncthreads();

    float oacc[6][4];
    #pragma unroll
    for (int nt = 0; nt < 6; nt++)
        #pragma unroll
        for (int e = 0; e < 4; e++) oacc[nt][e] = 0.f;
    float mr0 = -1e30f, mr1 = -1e30f, lr0 = 0.f, lr1 = 0.f;

    const float* Mr0 = mask + (long long)(b*N_ + q0 + m0 + gid)*N_;
    const float* Mr1 = Mr0 + 8LL*N_;

    int buf = 0;
    for (int kt = 0; kt < N_/64; kt++) {
        const int k0 = kt*64;
        if (kt + 1 < N_/64) {
            load_tile(buf ^ 1, k0 + 64);
            CP_COMMIT();
            CP_WAIT(1);
        } else {
            CP_WAIT(0);
        }
        __syncthreads();

        const float* Kb = Kd + buf*AT_K_W;
        const float* Vb = Vd + buf*AT_V_W;

        float2 mv0[8], mv1[8];
        #pragma unroll
        for (int nt = 0; nt < 8; nt++) {
            mv0[nt] = *(const float2*)(Mr0 + k0 + nt*8 + tg*2);
            mv1[nt] = *(const float2*)(Mr1 + k0 + nt*8 + tg*2);
        }

        float sacc[8][4];
        #pragma unroll
        for (int nt = 0; nt < 8; nt++)
            #pragma unroll
            for (int e = 0; e < 4; e++) sacc[nt][e] = 0.f;
        #pragma unroll
        for (int ks = 0; ks < 6; ks++) {
            const int kb = ks*8;
            uint32_t bf[8][2];
            #pragma unroll
            for (int nt = 0; nt < 8; nt++) {
                bf[nt][0] = __float_as_uint(Kb[(nt*8+gid)*AT_KSTR + kb+tg]);
                bf[nt][1] = __float_as_uint(Kb[(nt*8+gid)*AT_KSTR + kb+tg+4]);
            }
            #pragma unroll
            for (int nt = 0; nt < 8; nt++)
                mma_tf32(sacc[nt], qf[ks], bf[nt]);
        }

        float mx0 = mr0, mx1 = mr1;
        #pragma unroll
        for (int nt = 0; nt < 8; nt++) {
            float v0 = sacc[nt][0]*SCALE_ + mv0[nt].x;
            float v1 = sacc[nt][1]*SCALE_ + mv0[nt].y;
            float v2 = sacc[nt][2]*SCALE_ + mv1[nt].x;
            float v3 = sacc[nt][3]*SCALE_ + mv1[nt].y;
            sacc[nt][0] = v0; sacc[nt][1] = v1; sacc[nt][2] = v2; sacc[nt][3] = v3;
            mx0 = fmaxf(mx0, fmaxf(v0, v1));
            mx1 = fmaxf(mx1, fmaxf(v2, v3));
        }
        mx0 = fmaxf(mx0, __shfl_xor_sync(0xffffffffu, mx0, 1));
        mx0 = fmaxf(mx0, __shfl_xor_sync(0xffffffffu, mx0, 2));
        mx1 = fmaxf(mx1, __shfl_xor_sync(0xffffffffu, mx1, 1));
        mx1 = fmaxf(mx1, __shfl_xor_sync(0xffffffffu, mx1, 2));
        const float a0 = __expf(mr0 - mx0);
        const float a1 = __expf(mr1 - mx1);
        mr0 = mx0; mr1 = mx1;
        lr0 *= a0;  lr1 *= a1;
        #pragma unroll
        for (int nt = 0; nt < 6; nt++) {
            oacc[nt][0] *= a0; oacc[nt][1] *= a0;
            oacc[nt][2] *= a1; oacc[nt][3] *= a1;
        }
        float ps0 = 0.f, ps1 = 0.f;
        #pragma unroll
        for (int nt = 0; nt < 8; nt++) {
            const int col = nt*8 + tg*2;
            float p0 = __expf(sacc[nt][0] - mx0);
            float p1 = __expf(sacc[nt][1] - mx0);
            float p2 = __expf(sacc[nt][2] - mx1);
            float p3 = __expf(sacc[nt][3] - mx1);
            ps0 += p0 + p1;
            ps1 += p2 + p3;
            PsQ[(m0+gid  )*AT_PSTR + col  ] = p0;
            PsQ[(m0+gid  )*AT_PSTR + col+1] = p1;
            PsQ[(m0+gid+8)*AT_PSTR + col  ] = p2;
            PsQ[(m0+gid+8)*AT_PSTR + col+1] = p3;
        }
        lr0 += ps0; lr1 += ps1;
        __syncwarp();

        #pragma unroll
        for (int ks = 0; ks < 8; ks++) {
            const int kb = ks*8;
            uint32_t af[4];
            af[0] = __float_as_uint(PsQ[(m0+gid  )*AT_PSTR + kb+tg]);
            af[1] = __float_as_uint(PsQ[(m0+gid+8)*AT_PSTR + kb+tg]);
            af[2] = __float_as_uint(PsQ[(m0+gid  )*AT_PSTR + kb+tg+4]);
            af[3] = __float_as_uint(PsQ[(m0+gid+8)*AT_PSTR + kb+tg+4]);
            #pragma unroll
            for (int nt = 0; nt < 6; nt++) {
                uint32_t bv[2];
                bv[0] = __float_as_uint(Vb[(kb+tg  )*AT_VSTR + nt*8+gid]);
                bv[1] = __float_as_uint(Vb[(kb+tg+4)*AT_VSTR + nt*8+gid]);
                mma_tf32(oacc[nt], af, bv);
            }
        }
        __syncthreads();
        buf ^= 1;
    }

    lr0 += __shfl_xor_sync(0xffffffffu, lr0, 1);
    lr0 += __shfl_xor_sync(0xffffffffu, lr0, 2);
    lr1 += __shfl_xor_sync(0xffffffffu, lr1, 1);
    lr1 += __shfl_xor_sync(0xffffffffu, lr1, 2);
    const float i0 = 1.0f / lr0;
    const float i1 = 1.0f / lr1;

    const long long r0 = (long long)(b*N_ + q0 + m0 + gid)*DIM_ + hh*HD_;
    const long long r1 = r0 + 8LL*DIM_;
    #pragma unroll
    for (int nt = 0; nt < 6; nt++) {
        const int col = nt*8 + tg*2;
        *(float2*)&g_O[r0 + col] = make_float2(oacc[nt][0]*i0, oacc[nt][1]*i0);
        *(float2*)&g_O[r1 + col] = make_float2(oacc[nt][2]*i1, oacc[nt][3]*i1);
    }
}

// ---------------- launch ------------------------------------------------------
extern "C" void kernel_launch(void* const* d_in, const int* in_sizes, int n_in,
                              void* d_out, int out_size)
{
    const float* x       = (const float*)d_in[0];
    const float* pos     = (const float*)d_in[1];
    const float* mask    = (const float*)d_in[2];
    const int*   npts    = (const int*)d_in[3];   // int32 (jax canonicalized)
    const float* norm1_w = (const float*)d_in[4];
    const float* norm2_w = (const float*)d_in[5];
    const float* w_qkv   = (const float*)d_in[6];
    const float* w_proj  = (const float*)d_in[7];
    const float* b_proj  = (const float*)d_in[8];
    const float* w1      = (const float*)d_in[9];
    const float* w2      = (const float*)d_in[10];
    const float* w3      = (const float*)d_in[11];
    float* out = (float*)d_out;

    float *xa, *O, *h, *hf, *gb;
    cudaGetSymbolAddress((void**)&xa, g_xa);
    cudaGetSymbolAddress((void**)&O,  g_O);
    cudaGetSymbolAddress((void**)&h,  g_h);
    cudaGetSymbolAddress((void**)&hf, g_hf);
    cudaGetSymbolAddress((void**)&gb, g_gb);

    cudaFuncSetAttribute(attn_tc_kernel,
                         cudaFuncAttributeMaxDynamicSharedMemorySize, AT_SMEM_BYTES);
    cudaFuncSetAttribute(gemm_glu_kernel,
                         cudaFuncAttributeMaxDynamicSharedMemorySize, GLU_SMEM_BYTES);
    cudaFuncSetAttribute(gemm_tc_kernel<DIM_, MODE_QKV>,
                         cudaFuncAttributeMaxDynamicSharedMemorySize, GEMM_SMEM_BYTES);
    cudaFuncSetAttribute(gemm_tc_kernel<DIM_, MODE_PROJ>,
                         cudaFuncAttributeMaxDynamicSharedMemorySize, GEMM_SMEM_BYTES);
    cudaFuncSetAttribute(gemm_tc_kernel<HID_, MODE_FINAL>,
                         cudaFuncAttributeMaxDynamicSharedMemorySize, GEMM_SMEM_BYTES);

    // 1) xa = rmsnorm(x) * norm1_w
    rmsnorm_kernel<<<M_, 128>>>(x, norm1_w, xa);

    // 2) qkv GEMM + pos add + split into Q/K/V [B,H,N,HD]
    gemm_tc_kernel<DIM_, MODE_QKV><<<dim3(3*DIM_/64, M_/64), 256, GEMM_SMEM_BYTES>>>(
        xa, w_qkv, nullptr, pos, nullptr, nullptr);

    // 3) attention -> g_O [B,N,H*HD]
    attn_tc_kernel<<<dim3(N_/64, B_*H_), 128, AT_SMEM_BYTES>>>(mask);

    // 4) h = x + O @ w_proj^T + b_proj
    gemm_tc_kernel<DIM_, MODE_PROJ><<<dim3(DIM_/64, M_/64), 256, GEMM_SMEM_BYTES>>>(
        O, w_proj, h, b_proj, x, nullptr);

    // 5) hf = rmsnorm(h) * norm2_w
    rmsnorm_kernel<<<M_, 128>>>(h, norm2_w, hf);

    // 6+7) g = silu(hf @ w1^T) * (hf @ w3^T)   (fused GLU)
    gemm_glu_kernel<<<dim3(HID_/64, M_/64), 256, GLU_SMEM_BYTES>>>(
        hf, w1, w3, gb);

    // 8) out = keep ? h + g @ w2^T : 0
    gemm_tc_kernel<HID_, MODE_FINAL><<<dim3(DIM_/64, M_/64), 256, GEMM_SMEM_BYTES>>>(
        gb, w2, out, nullptr, h, npts);
}

// round 15
// speedup vs baseline: 1.0934x; 1.0934x over previous
#include <cuda_runtime.h>
#include <cstdint>

#define B_    4
#define N_    2048
#define DIM_  384
#define H_    8
#define HD_   48
#define HID_  1024
#define M_    (B_*N_)          // 8192
#define SCALE_ 0.14433756729740643f   // 48^-0.5
#define EPS_   1e-5f

// ---------------- scratch (no allocation allowed; __device__ globals) ----------
__device__ float g_xa [M_*DIM_];
__device__ float g_Q  [M_*DIM_];   // [B,H,N,HD]
__device__ float g_K  [M_*DIM_];
__device__ float g_V  [M_*DIM_];
__device__ float g_O  [M_*DIM_];   // [B,N,H*HD]
__device__ float g_h  [M_*DIM_];
__device__ float g_hf [M_*DIM_];
__device__ float g_gb [M_*HID_];

__device__ __forceinline__ void mma_tf32(float c[4], const uint32_t a[4], const uint32_t b[2]) {
    asm volatile(
        "mma.sync.aligned.m16n8k8.row.col.f32.tf32.tf32.f32 "
        "{%0,%1,%2,%3}, {%4,%5,%6,%7}, {%8,%9}, {%0,%1,%2,%3};"
        : "+f"(c[0]), "+f"(c[1]), "+f"(c[2]), "+f"(c[3])
        : "r"(a[0]), "r"(a[1]), "r"(a[2]), "r"(a[3]),
          "r"(b[0]), "r"(b[1]));
}

__device__ __forceinline__ uint32_t smem_u32(const void* p) {
    return (uint32_t)__cvta_generic_to_shared(p);
}
__device__ __forceinline__ void cp16(uint32_t dst, const void* src) {
    asm volatile("cp.async.cg.shared.global [%0], [%1], 16;" :: "r"(dst), "l"(src));
}
#define CP_COMMIT()  asm volatile("cp.async.commit_group;")
#define CP_WAIT(n)   asm volatile("cp.async.wait_group %0;" :: "n"(n))

// ---------------- RMSNorm: one row (384) per block of 128 threads --------------
__global__ void rmsnorm_kernel(const float* __restrict__ src,
                               const float* __restrict__ w,
                               float* __restrict__ dst) {
    const int row = blockIdx.x;
    const int tid = threadIdx.x;
    const float* xr = src + row*DIM_;
    float v0 = xr[tid], v1 = xr[tid+128], v2 = xr[tid+256];
    float s = v0*v0 + v1*v1 + v2*v2;
    #pragma unroll
    for (int o = 16; o > 0; o >>= 1) s += __shfl_xor_sync(0xffffffffu, s, o);
    __shared__ float red[4];
    if ((tid & 31) == 0) red[tid >> 5] = s;
    __syncthreads();
    float tot = red[0] + red[1] + red[2] + red[3];
    float sc = rsqrtf(tot * (1.0f/DIM_) + EPS_);
    float* dr = dst + row*DIM_;
    dr[tid]     = v0*sc*w[tid];
    dr[tid+128] = v1*sc*w[tid+128];
    dr[tid+256] = v2*sc*w[tid+256];
}

#define MODE_QKV   1
#define MODE_PROJ  2
#define MODE_FINAL 5

#define SSTR 36

// ---------------- 128x128-tile tf32 GEMM, BK=32, 256 thr (8 warps) -------------
// warp grid 2M x 4N, warp tile 64x32 -> 0.75 LDS per mma. 2-stage cp.async.
#define BSTG_W (128*SSTR)                      // 4608 words per matrix per stage
#define GEMM_SMEM_BYTES (2 * 2 * BSTG_W * 4)   // 73728

template<int KDIM, int MODE>
__global__ void __launch_bounds__(256, 2) gemm_tc_kernel(
    const float* __restrict__ A, const float* __restrict__ W,
    float* __restrict__ C,
    const float* __restrict__ aux1,   // pos | b_proj | -
    const float* __restrict__ aux2,   // -   | x      | h
    const int* __restrict__ npts)
{
    extern __shared__ float dsm[];
    float* As = dsm;                  // [2][BSTG_W]
    float* Bs = dsm + 2*BSTG_W;       // [2][BSTG_W]

    const int tid  = threadIdx.x;
    const int bm   = blockIdx.y << 7;
    const int bn   = blockIdx.x << 7;
    const int warp = tid >> 5;
    const int wm   = (warp >> 2) * 64;     // 2 M-slabs
    const int wn   = (warp & 3) * 32;      // 4 N-slabs
    const int lane = tid & 31;
    const int gid  = lane >> 2;
    const int tg   = lane & 3;

    const int r0 = tid >> 3;          // 0..31
    const int c0 = (tid & 7) << 2;    // 0,4,...,28

    float acc[4][4][4];
    #pragma unroll
    for (int mt = 0; mt < 4; mt++)
        #pragma unroll
        for (int nt = 0; nt < 4; nt++)
            #pragma unroll
            for (int e = 0; e < 4; e++) acc[mt][nt][e] = 0.f;

    const float* Ap = A + (long long)(bm + r0)*KDIM + c0;
    const float* Wp = W + (long long)(bn + r0)*KDIM + c0;
    const uint32_t dA = smem_u32(&As[r0*SSTR + c0]);
    const uint32_t dB = smem_u32(&Bs[r0*SSTR + c0]);

    auto load_stage = [&](int sbuf, int k0) {
        const uint32_t ob = (uint32_t)(sbuf * BSTG_W * 4);
        #pragma unroll
        for (int rr = 0; rr < 128; rr += 32) {
            cp16(dA + ob + (uint32_t)(rr*SSTR)*4, Ap + (long long)rr*KDIM + k0);
            cp16(dB + ob + (uint32_t)(rr*SSTR)*4, Wp + (long long)rr*KDIM + k0);
        }
    };

    constexpr int NK = KDIM / 32;
    load_stage(0, 0);
    CP_COMMIT();

    int buf = 0;
    for (int kt = 0; kt < NK; kt++) {
        if (kt + 1 < NK) {
            load_stage(buf ^ 1, (kt + 1) * 32);
            CP_COMMIT();
            CP_WAIT(1);
        } else {
            CP_WAIT(0);
        }
        __syncthreads();

        const float* Ab = As + buf*BSTG_W;
        const float* Bb = Bs + buf*BSTG_W;
        #pragma unroll
        for (int ks = 0; ks < 4; ks++) {
            const int kb = ks << 3;
            uint32_t af[4][4];
            uint32_t bf[4][2];
            #pragma unroll
            for (int mt = 0; mt < 4; mt++) {
                const int m0 = wm + mt*16;
                af[mt][0] = __float_as_uint(Ab[(m0+gid  )*SSTR + kb+tg]);
                af[mt][1] = __float_as_uint(Ab[(m0+gid+8)*SSTR + kb+tg]);
                af[mt][2] = __float_as_uint(Ab[(m0+gid  )*SSTR + kb+tg+4]);
                af[mt][3] = __float_as_uint(Ab[(m0+gid+8)*SSTR + kb+tg+4]);
            }
            #pragma unroll
            for (int nt = 0; nt < 4; nt++) {
                const int n0 = wn + nt*8;
                bf[nt][0] = __float_as_uint(Bb[(n0+gid)*SSTR + kb+tg]);
                bf[nt][1] = __float_as_uint(Bb[(n0+gid)*SSTR + kb+tg+4]);
            }
            #pragma unroll
            for (int mt = 0; mt < 4; mt++)
                #pragma unroll
                for (int nt = 0; nt < 4; nt++)
                    mma_tf32(acc[mt][nt], af[mt], bf[nt]);
        }
        __syncthreads();
        buf ^= 1;
    }

    #pragma unroll
    for (int mt = 0; mt < 4; mt++) {
        #pragma unroll
        for (int nt = 0; nt < 4; nt++) {
            #pragma unroll
            for (int e = 0; e < 4; e++) {
                const int m = bm + wm + mt*16 + gid + ((e & 2) ? 8 : 0);
                const int n = bn + wn + nt*8 + tg*2 + (e & 1);
                float v = acc[mt][nt][e];
                if constexpr (MODE == MODE_QKV) {
                    const int b    = m >> 11;
                    const int ns   = m & 2047;
                    const int part = n / DIM_;
                    const int rem  = n - part*DIM_;
                    const int hh   = rem / HD_;
                    const int hd   = rem - hh*HD_;
                    if (part < 2) v += aux1[(b*N_ + ns)*HD_ + hd];
                    float* dst = (part == 0) ? g_Q : (part == 1 ? g_K : g_V);
                    dst[(((b << 3) + hh)*N_ + ns)*HD_ + hd] = v;
                } else if constexpr (MODE == MODE_PROJ) {
                    C[m*DIM_ + n] = v + aux1[n] + aux2[m*DIM_ + n];
                } else if constexpr (MODE == MODE_FINAL) {
                    const int np = npts[m >> 11];
                    C[m*DIM_ + n] = ((m & 2047) < np)
                                    ? (aux2[m*DIM_ + n] + v) : 0.0f;
                }
            }
        }
    }
}

// ---------------- fused GLU GEMM (64x64, BK=32, 2 stages) — R13 config ---------
#define TSTG_W (64*SSTR)                       // 2304 words per matrix per stage
#define GLU_SMEM_BYTES  (3 * 2 * TSTG_W * 4)   // 55296

__global__ void __launch_bounds__(128, 4) gemm_glu_kernel(
    const float* __restrict__ A, const float* __restrict__ W1,
    const float* __restrict__ W3, float* __restrict__ C)
{
    extern __shared__ float gsm[];
    float* As = gsm;                   // [2][TSTG_W]
    float* B1 = gsm + 2*TSTG_W;
    float* B3 = gsm + 4*TSTG_W;

    const int tid  = threadIdx.x;
    const int bm   = blockIdx.y << 6;
    const int bn   = blockIdx.x << 6;
    const int warp = tid >> 5;
    const int wm   = (warp & 1) * 32;
    const int wn   = (warp >> 1) * 32;
    const int lane = tid & 31;
    const int gid  = lane >> 2;
    const int tg   = lane & 3;
    const int r0   = tid >> 3;
    const int c0   = (tid & 7) << 2;

    float acc1[2][4][4], acc3[2][4][4];
    #pragma unroll
    for (int mt = 0; mt < 2; mt++)
        #pragma unroll
        for (int nt = 0; nt < 4; nt++)
            #pragma unroll
            for (int e = 0; e < 4; e++) { acc1[mt][nt][e] = 0.f; acc3[mt][nt][e] = 0.f; }

    const float* Ap  = A  + (long long)(bm + r0)*DIM_ + c0;
    const float* W1p = W1 + (long long)(bn + r0)*DIM_ + c0;
    const float* W3p = W3 + (long long)(bn + r0)*DIM_ + c0;
    const uint32_t dA = smem_u32(&As[r0*SSTR + c0]);
    const uint32_t d1 = smem_u32(&B1[r0*SSTR + c0]);
    const uint32_t d3 = smem_u32(&B3[r0*SSTR + c0]);

    auto load_stage = [&](int sbuf, int k0) {
        const uint32_t ob = (uint32_t)(sbuf * TSTG_W * 4);
        #pragma unroll
        for (int rr = 0; rr < 64; rr += 16) {
            cp16(dA + ob + (uint32_t)(rr*SSTR)*4, Ap  + (long long)rr*DIM_ + k0);
            cp16(d1 + ob + (uint32_t)(rr*SSTR)*4, W1p + (long long)rr*DIM_ + k0);
            cp16(d3 + ob + (uint32_t)(rr*SSTR)*4, W3p + (long long)rr*DIM_ + k0);
        }
    };

    constexpr int NK = DIM_ / 32;      // 12
    load_stage(0, 0);
    CP_COMMIT();

    int buf = 0;
    for (int kt = 0; kt < NK; kt++) {
        if (kt + 1 < NK) {
            load_stage(buf ^ 1, (kt + 1) * 32);
            CP_COMMIT();
            CP_WAIT(1);
        } else {
            CP_WAIT(0);
        }
        __syncthreads();

        const float* Ab  = As + buf*TSTG_W;
        const float* B1b = B1 + buf*TSTG_W;
        const float* B3b = B3 + buf*TSTG_W;
        #pragma unroll
        for (int ks = 0; ks < 4; ks++) {
            const int kb = ks << 3;
            uint32_t af[2][4];
            #pragma unroll
            for (int mt = 0; mt < 2; mt++) {
                const int m0 = wm + mt*16;
                af[mt][0] = __float_as_uint(Ab[(m0+gid  )*SSTR + kb+tg]);
                af[mt][1] = __float_as_uint(Ab[(m0+gid+8)*SSTR + kb+tg]);
                af[mt][2] = __float_as_uint(Ab[(m0+gid  )*SSTR + kb+tg+4]);
                af[mt][3] = __float_as_uint(Ab[(m0+gid+8)*SSTR + kb+tg+4]);
            }
            #pragma unroll
            for (int nt = 0; nt < 4; nt++) {
                const int n0 = wn + nt*8;
                uint32_t b1f[2], b3f[2];
                b1f[0] = __float_as_uint(B1b[(n0+gid)*SSTR + kb+tg]);
                b1f[1] = __float_as_uint(B1b[(n0+gid)*SSTR + kb+tg+4]);
                b3f[0] = __float_as_uint(B3b[(n0+gid)*SSTR + kb+tg]);
                b3f[1] = __float_as_uint(B3b[(n0+gid)*SSTR + kb+tg+4]);
                #pragma unroll
                for (int mt = 0; mt < 2; mt++) {
                    mma_tf32(acc1[mt][nt], af[mt], b1f);
                    mma_tf32(acc3[mt][nt], af[mt], b3f);
                }
            }
        }
        __syncthreads();
        buf ^= 1;
    }

    #pragma unroll
    for (int mt = 0; mt < 2; mt++) {
        #pragma unroll
        for (int nt = 0; nt < 4; nt++) {
            #pragma unroll
            for (int e = 0; e < 4; e++) {
                const int m = bm + wm + mt*16 + gid + ((e & 2) ? 8 : 0);
                const int n = bn + wn + nt*8 + tg*2 + (e & 1);
                const float v1 = acc1[mt][nt][e];
                const float v3 = acc3[mt][nt][e];
                C[m*HID_ + n] = (v1 / (1.0f + __expf(-v1))) * v3;
            }
        }
    }
}

// ---------------- pipelined tensor-core flash attention (unchanged R8) ---------
#define AT_KSTR 52
#define AT_VSTR 56
#define AT_PSTR 68
#define AT_PSQ_W (64*AT_PSTR)
#define AT_K_W   (64*AT_KSTR)
#define AT_V_W   (64*AT_VSTR)
#define AT_SMEM_BYTES ((AT_PSQ_W + 2*AT_K_W + 2*AT_V_W) * 4)

__global__ void __launch_bounds__(128, 3) attn_tc_kernel(const float* __restrict__ mask) {
    extern __shared__ float sm[];
    float* PsQ = sm;
    float* Kd  = sm + AT_PSQ_W;
    float* Vd  = Kd + 2*AT_K_W;

    const int bh  = blockIdx.y;
    const int b   = bh >> 3;
    const int hh  = bh & 7;
    const int q0  = blockIdx.x * 64;
    const int tid = threadIdx.x;
    const int warp = tid >> 5;
    const int lane = tid & 31;
    const int gid  = lane >> 2;
    const int tg   = lane & 3;
    const int m0   = warp * 16;

    const float* Qbase = g_Q + ((long long)bh*N_ + q0)*HD_;
    const uint32_t qdst = smem_u32(PsQ);
    for (int i = tid; i < 64*12; i += 128) {
        const int row = i / 12, c = i - row*12;
        cp16(qdst + (uint32_t)(row*AT_KSTR + c*4)*4, Qbase + row*HD_ + c*4);
    }
    CP_COMMIT();

    const float* Kbase = g_K + (long long)bh*N_*HD_;
    const float* Vbase = g_V + (long long)bh*N_*HD_;
    const uint32_t kdst = smem_u32(Kd);
    const uint32_t vdst = smem_u32(Vd);

    auto load_tile = [&](int bufi, int k0) {
        const uint32_t kb = kdst + (uint32_t)(bufi*AT_K_W)*4;
        const uint32_t vb = vdst + (uint32_t)(bufi*AT_V_W)*4;
        for (int i = tid; i < 64*12; i += 128) {
            const int row = i / 12, c = i - row*12;
            cp16(kb + (uint32_t)(row*AT_KSTR + c*4)*4, Kbase + (k0+row)*HD_ + c*4);
            cp16(vb + (uint32_t)(row*AT_VSTR + c*4)*4, Vbase + (k0+row)*HD_ + c*4);
        }
    };

    load_tile(0, 0);
    CP_COMMIT();

    CP_WAIT(1);
    __syncthreads();
    uint32_t qf[6][4];
    #pragma unroll
    for (int ks = 0; ks < 6; ks++) {
        const int kb = ks*8;
        qf[ks][0] = __float_as_uint(PsQ[(m0+gid  )*AT_KSTR + kb+tg]);
        qf[ks][1] = __float_as_uint(PsQ[(m0+gid+8)*AT_KSTR + kb+tg]);
        qf[ks][2] = __float_as_uint(PsQ[(m0+gid  )*AT_KSTR + kb+tg+4]);
        qf[ks][3] = __float_as_uint(PsQ[(m0+gid+8)*AT_KSTR + kb+tg+4]);
    }
    __syncthreads();

    float oacc[6][4];
    #pragma unroll
    for (int nt = 0; nt < 6; nt++)
        #pragma unroll
        for (int e = 0; e < 4; e++) oacc[nt][e] = 0.f;
    float mr0 = -1e30f, mr1 = -1e30f, lr0 = 0.f, lr1 = 0.f;

    const float* Mr0 = mask + (long long)(b*N_ + q0 + m0 + gid)*N_;
    const float* Mr1 = Mr0 + 8LL*N_;

    int buf = 0;
    for (int kt = 0; kt < N_/64; kt++) {
        const int k0 = kt*64;
        if (kt + 1 < N_/64) {
            load_tile(buf ^ 1, k0 + 64);
            CP_COMMIT();
            CP_WAIT(1);
        } else {
            CP_WAIT(0);
        }
        __syncthreads();

        const float* Kb = Kd + buf*AT_K_W;
        const float* Vb = Vd + buf*AT_V_W;

        float2 mv0[8], mv1[8];
        #pragma unroll
        for (int nt = 0; nt < 8; nt++) {
            mv0[nt] = *(const float2*)(Mr0 + k0 + nt*8 + tg*2);
            mv1[nt] = *(const float2*)(Mr1 + k0 + nt*8 + tg*2);
        }

        float sacc[8][4];
        #pragma unroll
        for (int nt = 0; nt < 8; nt++)
            #pragma unroll
            for (int e = 0; e < 4; e++) sacc[nt][e] = 0.f;
        #pragma unroll
        for (int ks = 0; ks < 6; ks++) {
            const int kb = ks*8;
            uint32_t bf[8][2];
            #pragma unroll
            for (int nt = 0; nt < 8; nt++) {
                bf[nt][0] = __float_as_uint(Kb[(nt*8+gid)*AT_KSTR + kb+tg]);
                bf[nt][1] = __float_as_uint(Kb[(nt*8+gid)*AT_KSTR + kb+tg+4]);
            }
            #pragma unroll
            for (int nt = 0; nt < 8; nt++)
                mma_tf32(sacc[nt], qf[ks], bf[nt]);
        }

        float mx0 = mr0, mx1 = mr1;
        #pragma unroll
        for (int nt = 0; nt < 8; nt++) {
            float v0 = sacc[nt][0]*SCALE_ + mv0[nt].x;
            float v1 = sacc[nt][1]*SCALE_ + mv0[nt].y;
            float v2 = sacc[nt][2]*SCALE_ + mv1[nt].x;
            float v3 = sacc[nt][3]*SCALE_ + mv1[nt].y;
            sacc[nt][0] = v0; sacc[nt][1] = v1; sacc[nt][2] = v2; sacc[nt][3] = v3;
            mx0 = fmaxf(mx0, fmaxf(v0, v1));
            mx1 = fmaxf(mx1, fmaxf(v2, v3));
        }
        mx0 = fmaxf(mx0, __shfl_xor_sync(0xffffffffu, mx0, 1));
        mx0 = fmaxf(mx0, __shfl_xor_sync(0xffffffffu, mx0, 2));
        mx1 = fmaxf(mx1, __shfl_xor_sync(0xffffffffu, mx1, 1));
        mx1 = fmaxf(mx1, __shfl_xor_sync(0xffffffffu, mx1, 2));
        const float a0 = __expf(mr0 - mx0);
        const float a1 = __expf(mr1 - mx1);
        mr0 = mx0; mr1 = mx1;
        lr0 *= a0;  lr1 *= a1;
        #pragma unroll
        for (int nt = 0; nt < 6; nt++) {
            oacc[nt][0] *= a0; oacc[nt][1] *= a0;
            oacc[nt][2] *= a1; oacc[nt][3] *= a1;
        }
        float ps0 = 0.f, ps1 = 0.f;
        #pragma unroll
        for (int nt = 0; nt < 8; nt++) {
            const int col = nt*8 + tg*2;
            float p0 = __expf(sacc[nt][0] - mx0);
            float p1 = __expf(sacc[nt][1] - mx0);
            float p2 = __expf(sacc[nt][2] - mx1);
            float p3 = __expf(sacc[nt][3] - mx1);
            ps0 += p0 + p1;
            ps1 += p2 + p3;
            PsQ[(m0+gid  )*AT_PSTR + col  ] = p0;
            PsQ[(m0+gid  )*AT_PSTR + col+1] = p1;
            PsQ[(m0+gid+8)*AT_PSTR + col  ] = p2;
            PsQ[(m0+gid+8)*AT_PSTR + col+1] = p3;
        }
        lr0 += ps0; lr1 += ps1;
        __syncwarp();

        #pragma unroll
        for (int ks = 0; ks < 8; ks++) {
            const int kb = ks*8;
            uint32_t af[4];
            af[0] = __float_as_uint(PsQ[(m0+gid  )*AT_PSTR + kb+tg]);
            af[1] = __float_as_uint(PsQ[(m0+gid+8)*AT_PSTR + kb+tg]);
            af[2] = __float_as_uint(PsQ[(m0+gid  )*AT_PSTR + kb+tg+4]);
            af[3] = __float_as_uint(PsQ[(m0+gid+8)*AT_PSTR + kb+tg+4]);
            #pragma unroll
            for (int nt = 0; nt < 6; nt++) {
                uint32_t bv[2];
                bv[0] = __float_as_uint(Vb[(kb+tg  )*AT_VSTR + nt*8+gid]);
                bv[1] = __float_as_uint(Vb[(kb+tg+4)*AT_VSTR + nt*8+gid]);
                mma_tf32(oacc[nt], af, bv);
            }
        }
        __syncthreads();
        buf ^= 1;
    }

    lr0 += __shfl_xor_sync(0xffffffffu, lr0, 1);
    lr0 += __shfl_xor_sync(0xffffffffu, lr0, 2);
    lr1 += __shfl_xor_sync(0xffffffffu, lr1, 1);
    lr1 += __shfl_xor_sync(0xffffffffu, lr1, 2);
    const float i0 = 1.0f / lr0;
    const float i1 = 1.0f / lr1;

    const long long r0 = (long long)(b*N_ + q0 + m0 + gid)*DIM_ + hh*HD_;
    const long long r1 = r0 + 8LL*DIM_;
    #pragma unroll
    for (int nt = 0; nt < 6; nt++) {
        const int col = nt*8 + tg*2;
        *(float2*)&g_O[r0 + col] = make_float2(oacc[nt][0]*i0, oacc[nt][1]*i0);
        *(float2*)&g_O[r1 + col] = make_float2(oacc[nt][2]*i1, oacc[nt][3]*i1);
    }
}

// ---------------- launch ------------------------------------------------------
extern "C" void kernel_launch(void* const* d_in, const int* in_sizes, int n_in,
                              void* d_out, int out_size)
{
    const float* x       = (const float*)d_in[0];
    const float* pos     = (const float*)d_in[1];
    const float* mask    = (const float*)d_in[2];
    const int*   npts    = (const int*)d_in[3];   // int32 (jax canonicalized)
    const float* norm1_w = (const float*)d_in[4];
    const float* norm2_w = (const float*)d_in[5];
    const float* w_qkv   = (const float*)d_in[6];
    const float* w_proj  = (const float*)d_in[7];
    const float* b_proj  = (const float*)d_in[8];
    const float* w1      = (const float*)d_in[9];
    const float* w2      = (const float*)d_in[10];
    const float* w3      = (const float*)d_in[11];
    float* out = (float*)d_out;

    float *xa, *O, *h, *hf, *gb;
    cudaGetSymbolAddress((void**)&xa, g_xa);
    cudaGetSymbolAddress((void**)&O,  g_O);
    cudaGetSymbolAddress((void**)&h,  g_h);
    cudaGetSymbolAddress((void**)&hf, g_hf);
    cudaGetSymbolAddress((void**)&gb, g_gb);

    cudaFuncSetAttribute(attn_tc_kernel,
                         cudaFuncAttributeMaxDynamicSharedMemorySize, AT_SMEM_BYTES);
    cudaFuncSetAttribute(gemm_glu_kernel,
                         cudaFuncAttributeMaxDynamicSharedMemorySize, GLU_SMEM_BYTES);
    cudaFuncSetAttribute(gemm_tc_kernel<DIM_, MODE_QKV>,
                         cudaFuncAttributeMaxDynamicSharedMemorySize, GEMM_SMEM_BYTES);
    cudaFuncSetAttribute(gemm_tc_kernel<DIM_, MODE_PROJ>,
                         cudaFuncAttributeMaxDynamicSharedMemorySize, GEMM_SMEM_BYTES);
    cudaFuncSetAttribute(gemm_tc_kernel<HID_, MODE_FINAL>,
                         cudaFuncAttributeMaxDynamicSharedMemorySize, GEMM_SMEM_BYTES);

    // 1) xa = rmsnorm(x) * norm1_w
    rmsnorm_kernel<<<M_, 128>>>(x, norm1_w, xa);

    // 2) qkv GEMM + pos add + split into Q/K/V [B,H,N,HD]
    gemm_tc_kernel<DIM_, MODE_QKV><<<dim3(3*DIM_/128, M_/128), 256, GEMM_SMEM_BYTES>>>(
        xa, w_qkv, nullptr, pos, nullptr, nullptr);

    // 3) attention -> g_O [B,N,H*HD]
    attn_tc_kernel<<<dim3(N_/64, B_*H_), 128, AT_SMEM_BYTES>>>(mask);

    // 4) h = x + O @ w_proj^T + b_proj
    gemm_tc_kernel<DIM_, MODE_PROJ><<<dim3(DIM_/128, M_/128), 256, GEMM_SMEM_BYTES>>>(
        O, w_proj, h, b_proj, x, nullptr);

    // 5) hf = rmsnorm(h) * norm2_w
    rmsnorm_kernel<<<M_, 128>>>(h, norm2_w, hf);

    // 6+7) g = silu(hf @ w1^T) * (hf @ w3^T)   (fused GLU)
    gemm_glu_kernel<<<dim3(HID_/64, M_/64), 128, GLU_SMEM_BYTES>>>(
        hf, w1, w3, gb);

    // 8) out = keep ? h + g @ w2^T : 0
    gemm_tc_kernel<HID_, MODE_FINAL><<<dim3(DIM_/128, M_/128), 256, GEMM_SMEM_BYTES>>>(
        gb, w2, out, nullptr, h, npts);
}

// round 16
// speedup vs baseline: 1.1485x; 1.0504x over previous
#include <cuda_runtime.h>
#include <cstdint>

#define B_    4
#define N_    2048
#define DIM_  384
#define H_    8
#define HD_   48
#define HID_  1024
#define M_    (B_*N_)          // 8192
#define SCALE_ 0.14433756729740643f   // 48^-0.5
#define EPS_   1e-5f

// ---------------- scratch (no allocation allowed; __device__ globals) ----------
__device__ float g_xa [M_*DIM_];
__device__ float g_Q  [M_*DIM_];   // [B,H,N,HD]
__device__ float g_K  [M_*DIM_];
__device__ float g_V  [M_*DIM_];
__device__ float g_O  [M_*DIM_];   // [B,N,H*HD]
__device__ float g_h  [M_*DIM_];
__device__ float g_hf [M_*DIM_];
__device__ float g_gb [M_*HID_];

__device__ __forceinline__ void mma_tf32(float c[4], const uint32_t a[4], const uint32_t b[2]) {
    asm volatile(
        "mma.sync.aligned.m16n8k8.row.col.f32.tf32.tf32.f32 "
        "{%0,%1,%2,%3}, {%4,%5,%6,%7}, {%8,%9}, {%0,%1,%2,%3};"
        : "+f"(c[0]), "+f"(c[1]), "+f"(c[2]), "+f"(c[3])
        : "r"(a[0]), "r"(a[1]), "r"(a[2]), "r"(a[3]),
          "r"(b[0]), "r"(b[1]));
}
__device__ __forceinline__ void mma_tf32b(float c[4], const uint32_t a[4],
                                          uint32_t b0, uint32_t b1) {
    asm volatile(
        "mma.sync.aligned.m16n8k8.row.col.f32.tf32.tf32.f32 "
        "{%0,%1,%2,%3}, {%4,%5,%6,%7}, {%8,%9}, {%0,%1,%2,%3};"
        : "+f"(c[0]), "+f"(c[1]), "+f"(c[2]), "+f"(c[3])
        : "r"(a[0]), "r"(a[1]), "r"(a[2]), "r"(a[3]),
          "r"(b0), "r"(b1));
}

__device__ __forceinline__ void ldsm4(uint32_t r[4], uint32_t addr) {
    asm volatile("ldmatrix.sync.aligned.m8n8.x4.shared.b16 {%0,%1,%2,%3}, [%4];"
                 : "=r"(r[0]), "=r"(r[1]), "=r"(r[2]), "=r"(r[3]) : "r"(addr));
}

__device__ __forceinline__ uint32_t smem_u32(const void* p) {
    return (uint32_t)__cvta_generic_to_shared(p);
}
__device__ __forceinline__ void cp16(uint32_t dst, const void* src) {
    asm volatile("cp.async.cg.shared.global [%0], [%1], 16;" :: "r"(dst), "l"(src));
}
#define CP_COMMIT()  asm volatile("cp.async.commit_group;")
#define CP_WAIT(n)   asm volatile("cp.async.wait_group %0;" :: "n"(n))

// ---------------- RMSNorm: one row (384) per block of 128 threads --------------
__global__ void rmsnorm_kernel(const float* __restrict__ src,
                               const float* __restrict__ w,
                               float* __restrict__ dst) {
    const int row = blockIdx.x;
    const int tid = threadIdx.x;
    const float* xr = src + row*DIM_;
    float v0 = xr[tid], v1 = xr[tid+128], v2 = xr[tid+256];
    float s = v0*v0 + v1*v1 + v2*v2;
    #pragma unroll
    for (int o = 16; o > 0; o >>= 1) s += __shfl_xor_sync(0xffffffffu, s, o);
    __shared__ float red[4];
    if ((tid & 31) == 0) red[tid >> 5] = s;
    __syncthreads();
    float tot = red[0] + red[1] + red[2] + red[3];
    float sc = rsqrtf(tot * (1.0f/DIM_) + EPS_);
    float* dr = dst + row*DIM_;
    dr[tid]     = v0*sc*w[tid];
    dr[tid+128] = v1*sc*w[tid+128];
    dr[tid+256] = v2*sc*w[tid+256];
}

// ---------------- 64x64-tile tf32 GEMM, BK=32, ldmatrix frags ------------------
// 128 thr = 4 warps (2M x 2N), warp tile 32x32, 3-stage cp.async, stride 36.
// A m16k8 frag = one ldmatrix.x4; two n8 B-frags = one ldmatrix.x4.
#define MODE_QKV   1
#define MODE_PROJ  2
#define MODE_FINAL 5

#define SSTR 36
#define TSTG_W (64*SSTR)                       // 2304 words per matrix per stage
#define GEMM_SMEM_BYTES (2 * 3 * TSTG_W * 4)   // 55296
#define GLU_SMEM_BYTES  (3 * 2 * TSTG_W * 4)   // 55296

template<int KDIM, int MODE>
__global__ void __launch_bounds__(128, 4) gemm_tc_kernel(
    const float* __restrict__ A, const float* __restrict__ W,
    float* __restrict__ C,
    const float* __restrict__ aux1,   // pos | b_proj | -
    const float* __restrict__ aux2,   // -   | x      | h
    const int* __restrict__ npts)
{
    extern __shared__ float dsm[];
    float* As = dsm;                  // [3][TSTG_W]
    float* Bs = dsm + 3*TSTG_W;       // [3][TSTG_W]

    const int tid  = threadIdx.x;
    const int bm   = blockIdx.y << 6;
    const int bn   = blockIdx.x << 6;
    const int warp = tid >> 5;
    const int wm   = (warp & 1) * 32;
    const int wn   = (warp >> 1) * 32;
    const int lane = tid & 31;
    const int gid  = lane >> 2;
    const int tg   = lane & 3;

    const int r0 = tid >> 3;          // 0..15
    const int c0 = (tid & 7) << 2;    // 0,4,...,28

    // ldmatrix per-lane address offsets (in words, relative to tile base)
    const int a_off = (wm + ((lane>>3)&1)*8 + (lane&7))*SSTR + (lane>>4)*4;
    const int b_off = (wn + (lane>>4)*8 + (lane&7))*SSTR + ((lane>>3)&1)*4;

    float acc[2][4][4];
    #pragma unroll
    for (int mt = 0; mt < 2; mt++)
        #pragma unroll
        for (int nt = 0; nt < 4; nt++)
            #pragma unroll
            for (int e = 0; e < 4; e++) acc[mt][nt][e] = 0.f;

    const float* Ap = A + (long long)(bm + r0)*KDIM + c0;
    const float* Wp = W + (long long)(bn + r0)*KDIM + c0;
    const uint32_t dA = smem_u32(&As[r0*SSTR + c0]);
    const uint32_t dB = smem_u32(&Bs[r0*SSTR + c0]);
    const uint32_t Abase = smem_u32(As);
    const uint32_t Bbase = smem_u32(Bs);

    auto load_stage = [&](int sbuf, int k0) {
        const uint32_t ob = (uint32_t)(sbuf * TSTG_W * 4);
        #pragma unroll
        for (int rr = 0; rr < 64; rr += 16) {
            cp16(dA + ob + (uint32_t)(rr*SSTR)*4, Ap + (long long)rr*KDIM + k0);
            cp16(dB + ob + (uint32_t)(rr*SSTR)*4, Wp + (long long)rr*KDIM + k0);
        }
    };

    constexpr int NK = KDIM / 32;
    load_stage(0, 0);  CP_COMMIT();
    load_stage(1, 32); CP_COMMIT();

    int sb = 0;
    for (int kt = 0; kt < NK; kt++) {
        CP_WAIT(1);
        __syncthreads();
        if (kt + 2 < NK) {
            int nb = sb + 2; if (nb >= 3) nb -= 3;
            load_stage(nb, (kt + 2) * 32);
        }
        CP_COMMIT();

        const uint32_t Au = Abase + (uint32_t)(sb*TSTG_W)*4;
        const uint32_t Bu = Bbase + (uint32_t)(sb*TSTG_W)*4;
        #pragma unroll
        for (int ks = 0; ks < 4; ks++) {
            const int kb = ks << 3;
            uint32_t af[2][4];
            uint32_t bq[2][4];
            #pragma unroll
            for (int mt = 0; mt < 2; mt++)
                ldsm4(af[mt], Au + (uint32_t)(a_off + mt*16*SSTR + kb)*4);
            #pragma unroll
            for (int p = 0; p < 2; p++)
                ldsm4(bq[p], Bu + (uint32_t)(b_off + p*16*SSTR + kb)*4);
            #pragma unroll
            for (int mt = 0; mt < 2; mt++) {
                #pragma unroll
                for (int p = 0; p < 2; p++) {
                    mma_tf32b(acc[mt][2*p  ], af[mt], bq[p][0], bq[p][1]);
                    mma_tf32b(acc[mt][2*p+1], af[mt], bq[p][2], bq[p][3]);
                }
            }
        }
        if (++sb == 3) sb = 0;
    }

    #pragma unroll
    for (int mt = 0; mt < 2; mt++) {
        #pragma unroll
        for (int nt = 0; nt < 4; nt++) {
            #pragma unroll
            for (int e = 0; e < 4; e++) {
                const int m = bm + wm + mt*16 + gid + ((e & 2) ? 8 : 0);
                const int n = bn + wn + nt*8 + tg*2 + (e & 1);
                float v = acc[mt][nt][e];
                if constexpr (MODE == MODE_QKV) {
                    const int b    = m >> 11;
                    const int ns   = m & 2047;
                    const int part = n / DIM_;
                    const int rem  = n - part*DIM_;
                    const int hh   = rem / HD_;
                    const int hd   = rem - hh*HD_;
                    if (part < 2) v += aux1[(b*N_ + ns)*HD_ + hd];
                    float* dst = (part == 0) ? g_Q : (part == 1 ? g_K : g_V);
                    dst[(((b << 3) + hh)*N_ + ns)*HD_ + hd] = v;
                } else if constexpr (MODE == MODE_PROJ) {
                    C[m*DIM_ + n] = v + aux1[n] + aux2[m*DIM_ + n];
                } else if constexpr (MODE == MODE_FINAL) {
                    const int np = npts[m >> 11];
                    C[m*DIM_ + n] = ((m & 2047) < np)
                                    ? (aux2[m*DIM_ + n] + v) : 0.0f;
                }
            }
        }
    }
}

// ---------------- fused GLU GEMM (64x64, BK=32, 2 stages, ldmatrix) ------------
__global__ void __launch_bounds__(128, 4) gemm_glu_kernel(
    const float* __restrict__ A, const float* __restrict__ W1,
    const float* __restrict__ W3, float* __restrict__ C)
{
    extern __shared__ float gsm[];
    float* As = gsm;                   // [2][TSTG_W]
    float* B1 = gsm + 2*TSTG_W;
    float* B3 = gsm + 4*TSTG_W;

    const int tid  = threadIdx.x;
    const int bm   = blockIdx.y << 6;
    const int bn   = blockIdx.x << 6;
    const int warp = tid >> 5;
    const int wm   = (warp & 1) * 32;
    const int wn   = (warp >> 1) * 32;
    const int lane = tid & 31;
    const int gid  = lane >> 2;
    const int tg   = lane & 3;
    const int r0   = tid >> 3;
    const int c0   = (tid & 7) << 2;

    const int a_off = (wm + ((lane>>3)&1)*8 + (lane&7))*SSTR + (lane>>4)*4;
    const int b_off = (wn + (lane>>4)*8 + (lane&7))*SSTR + ((lane>>3)&1)*4;

    float acc1[2][4][4], acc3[2][4][4];
    #pragma unroll
    for (int mt = 0; mt < 2; mt++)
        #pragma unroll
        for (int nt = 0; nt < 4; nt++)
            #pragma unroll
            for (int e = 0; e < 4; e++) { acc1[mt][nt][e] = 0.f; acc3[mt][nt][e] = 0.f; }

    const float* Ap  = A  + (long long)(bm + r0)*DIM_ + c0;
    const float* W1p = W1 + (long long)(bn + r0)*DIM_ + c0;
    const float* W3p = W3 + (long long)(bn + r0)*DIM_ + c0;
    const uint32_t dA = smem_u32(&As[r0*SSTR + c0]);
    const uint32_t d1 = smem_u32(&B1[r0*SSTR + c0]);
    const uint32_t d3 = smem_u32(&B3[r0*SSTR + c0]);
    const uint32_t Abase = smem_u32(As);
    const uint32_t B1base = smem_u32(B1);
    const uint32_t B3base = smem_u32(B3);

    auto load_stage = [&](int sbuf, int k0) {
        const uint32_t ob = (uint32_t)(sbuf * TSTG_W * 4);
        #pragma unroll
        for (int rr = 0; rr < 64; rr += 16) {
            cp16(dA + ob + (uint32_t)(rr*SSTR)*4, Ap  + (long long)rr*DIM_ + k0);
            cp16(d1 + ob + (uint32_t)(rr*SSTR)*4, W1p + (long long)rr*DIM_ + k0);
            cp16(d3 + ob + (uint32_t)(rr*SSTR)*4, W3p + (long long)rr*DIM_ + k0);
        }
    };

    constexpr int NK = DIM_ / 32;      // 12
    load_stage(0, 0);
    CP_COMMIT();

    int buf = 0;
    for (int kt = 0; kt < NK; kt++) {
        if (kt + 1 < NK) {
            load_stage(buf ^ 1, (kt + 1) * 32);
            CP_COMMIT();
            CP_WAIT(1);
        } else {
            CP_WAIT(0);
        }
        __syncthreads();

        const uint32_t Au  = Abase  + (uint32_t)(buf*TSTG_W)*4;
        const uint32_t B1u = B1base + (uint32_t)(buf*TSTG_W)*4;
        const uint32_t B3u = B3base + (uint32_t)(buf*TSTG_W)*4;
        #pragma unroll
        for (int ks = 0; ks < 4; ks++) {
            const int kb = ks << 3;
            uint32_t af[2][4];
            uint32_t q1[2][4], q3[2][4];
            #pragma unroll
            for (int mt = 0; mt < 2; mt++)
                ldsm4(af[mt], Au + (uint32_t)(a_off + mt*16*SSTR + kb)*4);
            #pragma unroll
            for (int p = 0; p < 2; p++) {
                ldsm4(q1[p], B1u + (uint32_t)(b_off + p*16*SSTR + kb)*4);
                ldsm4(q3[p], B3u + (uint32_t)(b_off + p*16*SSTR + kb)*4);
            }
            #pragma unroll
            for (int mt = 0; mt < 2; mt++) {
                #pragma unroll
                for (int p = 0; p < 2; p++) {
                    mma_tf32b(acc1[mt][2*p  ], af[mt], q1[p][0], q1[p][1]);
                    mma_tf32b(acc1[mt][2*p+1], af[mt], q1[p][2], q1[p][3]);
                    mma_tf32b(acc3[mt][2*p  ], af[mt], q3[p][0], q3[p][1]);
                    mma_tf32b(acc3[mt][2*p+1], af[mt], q3[p][2], q3[p][3]);
                }
            }
        }
        __syncthreads();
        buf ^= 1;
    }

    #pragma unroll
    for (int mt = 0; mt < 2; mt++) {
        #pragma unroll
        for (int nt = 0; nt < 4; nt++) {
            #pragma unroll
            for (int e = 0; e < 4; e++) {
                const int m = bm + wm + mt*16 + gid + ((e & 2) ? 8 : 0);
                const int n = bn + wn + nt*8 + tg*2 + (e & 1);
                const float v1 = acc1[mt][nt][e];
                const float v3 = acc3[mt][nt][e];
                C[m*HID_ + n] = (v1 / (1.0f + __expf(-v1))) * v3;
            }
        }
    }
}

// ---------------- pipelined tensor-core flash attention (unchanged R8) ---------
#define AT_KSTR 52
#define AT_VSTR 56
#define AT_PSTR 68
#define AT_PSQ_W (64*AT_PSTR)
#define AT_K_W   (64*AT_KSTR)
#define AT_V_W   (64*AT_VSTR)
#define AT_SMEM_BYTES ((AT_PSQ_W + 2*AT_K_W + 2*AT_V_W) * 4)

__global__ void __launch_bounds__(128, 3) attn_tc_kernel(const float* __restrict__ mask) {
    extern __shared__ float sm[];
    float* PsQ = sm;
    float* Kd  = sm + AT_PSQ_W;
    float* Vd  = Kd + 2*AT_K_W;

    const int bh  = blockIdx.y;
    const int b   = bh >> 3;
    const int hh  = bh & 7;
    const int q0  = blockIdx.x * 64;
    const int tid = threadIdx.x;
    const int warp = tid >> 5;
    const int lane = tid & 31;
    const int gid  = lane >> 2;
    const int tg   = lane & 3;
    const int m0   = warp * 16;

    const float* Qbase = g_Q + ((long long)bh*N_ + q0)*HD_;
    const uint32_t qdst = smem_u32(PsQ);
    for (int i = tid; i < 64*12; i += 128) {
        const int row = i / 12, c = i - row*12;
        cp16(qdst + (uint32_t)(row*AT_KSTR + c*4)*4, Qbase + row*HD_ + c*4);
    }
    CP_COMMIT();

    const float* Kbase = g_K + (long long)bh*N_*HD_;
    const float* Vbase = g_V + (long long)bh*N_*HD_;
    const uint32_t kdst = smem_u32(Kd);
    const uint32_t vdst = smem_u32(Vd);

    auto load_tile = [&](int bufi, int k0) {
        const uint32_t kb = kdst + (uint32_t)(bufi*AT_K_W)*4;
        const uint32_t vb = vdst + (uint32_t)(bufi*AT_V_W)*4;
        for (int i = tid; i < 64*12; i += 128) {
            const int row = i / 12, c = i - row*12;
            cp16(kb + (uint32_t)(row*AT_KSTR + c*4)*4, Kbase + (k0+row)*HD_ + c*4);
            cp16(vb + (uint32_t)(row*AT_VSTR + c*4)*4, Vbase + (k0+row)*HD_ + c*4);
        }
    };

    load_tile(0, 0);
    CP_COMMIT();

    CP_WAIT(1);
    __syncthreads();
    uint32_t qf[6][4];
    #pragma unroll
    for (int ks = 0; ks < 6; ks++) {
        const int kb = ks*8;
        qf[ks][0] = __float_as_uint(PsQ[(m0+gid  )*AT_KSTR + kb+tg]);
        qf[ks][1] = __float_as_uint(PsQ[(m0+gid+8)*AT_KSTR + kb+tg]);
        qf[ks][2] = __float_as_uint(PsQ[(m0+gid  )*AT_KSTR + kb+tg+4]);
        qf[ks][3] = __float_as_uint(PsQ[(m0+gid+8)*AT_KSTR + kb+tg+4]);
    }
    __syncthreads();

    float oacc[6][4];
    #pragma unroll
    for (int nt = 0; nt < 6; nt++)
        #pragma unroll
        for (int e = 0; e < 4; e++) oacc[nt][e] = 0.f;
    float mr0 = -1e30f, mr1 = -1e30f, lr0 = 0.f, lr1 = 0.f;

    const float* Mr0 = mask + (long long)(b*N_ + q0 + m0 + gid)*N_;
    const float* Mr1 = Mr0 + 8LL*N_;

    int buf = 0;
    for (int kt = 0; kt < N_/64; kt++) {
        const int k0 = kt*64;
        if (kt + 1 < N_/64) {
            load_tile(buf ^ 1, k0 + 64);
            CP_COMMIT();
            CP_WAIT(1);
        } else {
            CP_WAIT(0);
        }
        __syncthreads();

        const float* Kb = Kd + buf*AT_K_W;
        const float* Vb = Vd + buf*AT_V_W;

        float2 mv0[8], mv1[8];
        #pragma unroll
        for (int nt = 0; nt < 8; nt++) {
            mv0[nt] = *(const float2*)(Mr0 + k0 + nt*8 + tg*2);
            mv1[nt] = *(const float2*)(Mr1 + k0 + nt*8 + tg*2);
        }

        float sacc[8][4];
        #pragma unroll
        for (int nt = 0; nt < 8; nt++)
            #pragma unroll
            for (int e = 0; e < 4; e++) sacc[nt][e] = 0.f;
        #pragma unroll
        for (int ks = 0; ks < 6; ks++) {
            const int kb = ks*8;
            uint32_t bf[8][2];
            #pragma unroll
            for (int nt = 0; nt < 8; nt++) {
                bf[nt][0] = __float_as_uint(Kb[(nt*8+gid)*AT_KSTR + kb+tg]);
                bf[nt][1] = __float_as_uint(Kb[(nt*8+gid)*AT_KSTR + kb+tg+4]);
            }
            #pragma unroll
            for (int nt = 0; nt < 8; nt++)
                mma_tf32(sacc[nt], qf[ks], bf[nt]);
        }

        float mx0 = mr0, mx1 = mr1;
        #pragma unroll
        for (int nt = 0; nt < 8; nt++) {
            float v0 = sacc[nt][0]*SCALE_ + mv0[nt].x;
            float v1 = sacc[nt][1]*SCALE_ + mv0[nt].y;
            float v2 = sacc[nt][2]*SCALE_ + mv1[nt].x;
            float v3 = sacc[nt][3]*SCALE_ + mv1[nt].y;
            sacc[nt][0] = v0; sacc[nt][1] = v1; sacc[nt][2] = v2; sacc[nt][3] = v3;
            mx0 = fmaxf(mx0, fmaxf(v0, v1));
            mx1 = fmaxf(mx1, fmaxf(v2, v3));
        }
        mx0 = fmaxf(mx0, __shfl_xor_sync(0xffffffffu, mx0, 1));
        mx0 = fmaxf(mx0, __shfl_xor_sync(0xffffffffu, mx0, 2));
        mx1 = fmaxf(mx1, __shfl_xor_sync(0xffffffffu, mx1, 1));
        mx1 = fmaxf(mx1, __shfl_xor_sync(0xffffffffu, mx1, 2));
        const float a0 = __expf(mr0 - mx0);
        const float a1 = __expf(mr1 - mx1);
        mr0 = mx0; mr1 = mx1;
        lr0 *= a0;  lr1 *= a1;
        #pragma unroll
        for (int nt = 0; nt < 6; nt++) {
            oacc[nt][0] *= a0; oacc[nt][1] *= a0;
            oacc[nt][2] *= a1; oacc[nt][3] *= a1;
        }
        float ps0 = 0.f, ps1 = 0.f;
        #pragma unroll
        for (int nt = 0; nt < 8; nt++) {
            const int col = nt*8 + tg*2;
            float p0 = __expf(sacc[nt][0] - mx0);
            float p1 = __expf(sacc[nt][1] - mx0);
            float p2 = __expf(sacc[nt][2] - mx1);
            float p3 = __expf(sacc[nt][3] - mx1);
            ps0 += p0 + p1;
            ps1 += p2 + p3;
            PsQ[(m0+gid  )*AT_PSTR + col  ] = p0;
            PsQ[(m0+gid  )*AT_PSTR + col+1] = p1;
            PsQ[(m0+gid+8)*AT_PSTR + col  ] = p2;
            PsQ[(m0+gid+8)*AT_PSTR + col+1] = p3;
        }
        lr0 += ps0; lr1 += ps1;
        __syncwarp();

        #pragma unroll
        for (int ks = 0; ks < 8; ks++) {
            const int kb = ks*8;
            uint32_t af[4];
            af[0] = __float_as_uint(PsQ[(m0+gid  )*AT_PSTR + kb+tg]);
            af[1] = __float_as_uint(PsQ[(m0+gid+8)*AT_PSTR + kb+tg]);
            af[2] = __float_as_uint(PsQ[(m0+gid  )*AT_PSTR + kb+tg+4]);
            af[3] = __float_as_uint(PsQ[(m0+gid+8)*AT_PSTR + kb+tg+4]);
            #pragma unroll
            for (int nt = 0; nt < 6; nt++) {
                uint32_t bv[2];
                bv[0] = __float_as_uint(Vb[(kb+tg  )*AT_VSTR + nt*8+gid]);
                bv[1] = __float_as_uint(Vb[(kb+tg+4)*AT_VSTR + nt*8+gid]);
                mma_tf32(oacc[nt], af, bv);
            }
        }
        __syncthreads();
        buf ^= 1;
    }

    lr0 += __shfl_xor_sync(0xffffffffu, lr0, 1);
    lr0 += __shfl_xor_sync(0xffffffffu, lr0, 2);
    lr1 += __shfl_xor_sync(0xffffffffu, lr1, 1);
    lr1 += __shfl_xor_sync(0xffffffffu, lr1, 2);
    const float i0 = 1.0f / lr0;
    const float i1 = 1.0f / lr1;

    const long long r0 = (long long)(b*N_ + q0 + m0 + gid)*DIM_ + hh*HD_;
    const long long r1 = r0 + 8LL*DIM_;
    #pragma unroll
    for (int nt = 0; nt < 6; nt++) {
        const int col = nt*8 + tg*2;
        *(float2*)&g_O[r0 + col] = make_float2(oacc[nt][0]*i0, oacc[nt][1]*i0);
        *(float2*)&g_O[r1 + col] = make_float2(oacc[nt][2]*i1, oacc[nt][3]*i1);
    }
}

// ---------------- launch ------------------------------------------------------
extern "C" void kernel_launch(void* const* d_in, const int* in_sizes, int n_in,
                              void* d_out, int out_size)
{
    const float* x       = (const float*)d_in[0];
    const float* pos     = (const float*)d_in[1];
    const float* mask    = (const float*)d_in[2];
    const int*   npts    = (const int*)d_in[3];   // int32 (jax canonicalized)
    const float* norm1_w = (const float*)d_in[4];
    const float* norm2_w = (const float*)d_in[5];
    const float* w_qkv   = (const float*)d_in[6];
    const float* w_proj  = (const float*)d_in[7];
    const float* b_proj  = (const float*)d_in[8];
    const float* w1      = (const float*)d_in[9];
    const float* w2      = (const float*)d_in[10];
    const float* w3      = (const float*)d_in[11];
    float* out = (float*)d_out;

    float *xa, *O, *h, *hf, *gb;
    cudaGetSymbolAddress((void**)&xa, g_xa);
    cudaGetSymbolAddress((void**)&O,  g_O);
    cudaGetSymbolAddress((void**)&h,  g_h);
    cudaGetSymbolAddress((void**)&hf, g_hf);
    cudaGetSymbolAddress((void**)&gb, g_gb);

    cudaFuncSetAttribute(attn_tc_kernel,
                         cudaFuncAttributeMaxDynamicSharedMemorySize, AT_SMEM_BYTES);
    cudaFuncSetAttribute(gemm_glu_kernel,
                         cudaFuncAttributeMaxDynamicSharedMemorySize, GLU_SMEM_BYTES);
    cudaFuncSetAttribute(gemm_tc_kernel<DIM_, MODE_QKV>,
                         cudaFuncAttributeMaxDynamicSharedMemorySize, GEMM_SMEM_BYTES);
    cudaFuncSetAttribute(gemm_tc_kernel<DIM_, MODE_PROJ>,
                         cudaFuncAttributeMaxDynamicSharedMemorySize, GEMM_SMEM_BYTES);
    cudaFuncSetAttribute(gemm_tc_kernel<HID_, MODE_FINAL>,
                         cudaFuncAttributeMaxDynamicSharedMemorySize, GEMM_SMEM_BYTES);

    // 1) xa = rmsnorm(x) * norm1_w
    rmsnorm_kernel<<<M_, 128>>>(x, norm1_w, xa);

    // 2) qkv GEMM + pos add + split into Q/K/V [B,H,N,HD]
    gemm_tc_kernel<DIM_, MODE_QKV><<<dim3(3*DIM_/64, M_/64), 128, GEMM_SMEM_BYTES>>>(
        xa, w_qkv, nullptr, pos, nullptr, nullptr);

    // 3) attention -> g_O [B,N,H*HD]
    attn_tc_kernel<<<dim3(N_/64, B_*H_), 128, AT_SMEM_BYTES>>>(mask);

    // 4) h = x + O @ w_proj^T + b_proj
    gemm_tc_kernel<DIM_, MODE_PROJ><<<dim3(DIM_/64, M_/64), 128, GEMM_SMEM_BYTES>>>(
        O, w_proj, h, b_proj, x, nullptr);

    // 5) hf = rmsnorm(h) * norm2_w
    rmsnorm_kernel<<<M_, 128>>>(h, norm2_w, hf);

    // 6+7) g = silu(hf @ w1^T) * (hf @ w3^T)   (fused GLU)
    gemm_glu_kernel<<<dim3(HID_/64, M_/64), 128, GLU_SMEM_BYTES>>>(
        hf, w1, w3, gb);

    // 8) out = keep ? h + g @ w2^T : 0
    gemm_tc_kernel<HID_, MODE_FINAL><<<dim3(DIM_/64, M_/64), 128, GEMM_SMEM_BYTES>>>(
        gb, w2, out, nullptr, h, npts);
}

// round 17
// speedup vs baseline: 1.1778x; 1.0256x over previous
#include <cuda_runtime.h>
#include <cstdint>

#define B_    4
#define N_    2048
#define DIM_  384
#define H_    8
#define HD_   48
#define HID_  1024
#define M_    (B_*N_)          // 8192
#define SCALE_ 0.14433756729740643f   // 48^-0.5
#define EPS_   1e-5f

// ---------------- scratch (no allocation allowed; __device__ globals) ----------
__device__ float g_xa [M_*DIM_];
__device__ float g_Q  [M_*DIM_];   // [B,H,N,HD]
__device__ float g_K  [M_*DIM_];
__device__ float g_V  [M_*DIM_];
__device__ float g_O  [M_*DIM_];   // [B,N,H*HD]
__device__ float g_h  [M_*DIM_];
__device__ float g_hf [M_*DIM_];
__device__ float g_gb [M_*HID_];

__device__ __forceinline__ void mma_tf32(float c[4], const uint32_t a[4], const uint32_t b[2]) {
    asm volatile(
        "mma.sync.aligned.m16n8k8.row.col.f32.tf32.tf32.f32 "
        "{%0,%1,%2,%3}, {%4,%5,%6,%7}, {%8,%9}, {%0,%1,%2,%3};"
        : "+f"(c[0]), "+f"(c[1]), "+f"(c[2]), "+f"(c[3])
        : "r"(a[0]), "r"(a[1]), "r"(a[2]), "r"(a[3]),
          "r"(b[0]), "r"(b[1]));
}
__device__ __forceinline__ void mma_tf32b(float c[4], const uint32_t a[4],
                                          uint32_t b0, uint32_t b1) {
    asm volatile(
        "mma.sync.aligned.m16n8k8.row.col.f32.tf32.tf32.f32 "
        "{%0,%1,%2,%3}, {%4,%5,%6,%7}, {%8,%9}, {%0,%1,%2,%3};"
        : "+f"(c[0]), "+f"(c[1]), "+f"(c[2]), "+f"(c[3])
        : "r"(a[0]), "r"(a[1]), "r"(a[2]), "r"(a[3]),
          "r"(b0), "r"(b1));
}

__device__ __forceinline__ void ldsm4(uint32_t r[4], uint32_t addr) {
    asm volatile("ldmatrix.sync.aligned.m8n8.x4.shared.b16 {%0,%1,%2,%3}, [%4];"
                 : "=r"(r[0]), "=r"(r[1]), "=r"(r[2]), "=r"(r[3]) : "r"(addr));
}

__device__ __forceinline__ uint32_t smem_u32(const void* p) {
    return (uint32_t)__cvta_generic_to_shared(p);
}
__device__ __forceinline__ void cp16(uint32_t dst, const void* src) {
    asm volatile("cp.async.cg.shared.global [%0], [%1], 16;" :: "r"(dst), "l"(src));
}
#define CP_COMMIT()  asm volatile("cp.async.commit_group;")
#define CP_WAIT(n)   asm volatile("cp.async.wait_group %0;" :: "n"(n))

// ---------------- RMSNorm: one row (384) per block of 128 threads --------------
__global__ void rmsnorm_kernel(const float* __restrict__ src,
                               const float* __restrict__ w,
                               float* __restrict__ dst) {
    const int row = blockIdx.x;
    const int tid = threadIdx.x;
    const float* xr = src + row*DIM_;
    float v0 = xr[tid], v1 = xr[tid+128], v2 = xr[tid+256];
    float s = v0*v0 + v1*v1 + v2*v2;
    #pragma unroll
    for (int o = 16; o > 0; o >>= 1) s += __shfl_xor_sync(0xffffffffu, s, o);
    __shared__ float red[4];
    if ((tid & 31) == 0) red[tid >> 5] = s;
    __syncthreads();
    float tot = red[0] + red[1] + red[2] + red[3];
    float sc = rsqrtf(tot * (1.0f/DIM_) + EPS_);
    float* dr = dst + row*DIM_;
    dr[tid]     = v0*sc*w[tid];
    dr[tid+128] = v1*sc*w[tid+128];
    dr[tid+256] = v2*sc*w[tid+256];
}

// ---------------- 64x64-tile tf32 GEMM, BK=32, ldmatrix frags (R16) ------------
#define MODE_QKV   1
#define MODE_PROJ  2
#define MODE_FINAL 5

#define SSTR 36
#define TSTG_W (64*SSTR)
#define GEMM_SMEM_BYTES (2 * 3 * TSTG_W * 4)   // 55296
#define GLU_SMEM_BYTES  (3 * 2 * TSTG_W * 4)   // 55296

template<int KDIM, int MODE>
__global__ void __launch_bounds__(128, 4) gemm_tc_kernel(
    const float* __restrict__ A, const float* __restrict__ W,
    float* __restrict__ C,
    const float* __restrict__ aux1,
    const float* __restrict__ aux2,
    const int* __restrict__ npts)
{
    extern __shared__ float dsm[];
    float* As = dsm;
    float* Bs = dsm + 3*TSTG_W;

    const int tid  = threadIdx.x;
    const int bm   = blockIdx.y << 6;
    const int bn   = blockIdx.x << 6;
    const int warp = tid >> 5;
    const int wm   = (warp & 1) * 32;
    const int wn   = (warp >> 1) * 32;
    const int lane = tid & 31;
    const int gid  = lane >> 2;
    const int tg   = lane & 3;

    const int r0 = tid >> 3;
    const int c0 = (tid & 7) << 2;

    const int a_off = (wm + ((lane>>3)&1)*8 + (lane&7))*SSTR + (lane>>4)*4;
    const int b_off = (wn + (lane>>4)*8 + (lane&7))*SSTR + ((lane>>3)&1)*4;

    float acc[2][4][4];
    #pragma unroll
    for (int mt = 0; mt < 2; mt++)
        #pragma unroll
        for (int nt = 0; nt < 4; nt++)
            #pragma unroll
            for (int e = 0; e < 4; e++) acc[mt][nt][e] = 0.f;

    const float* Ap = A + (long long)(bm + r0)*KDIM + c0;
    const float* Wp = W + (long long)(bn + r0)*KDIM + c0;
    const uint32_t dA = smem_u32(&As[r0*SSTR + c0]);
    const uint32_t dB = smem_u32(&Bs[r0*SSTR + c0]);
    const uint32_t Abase = smem_u32(As);
    const uint32_t Bbase = smem_u32(Bs);

    auto load_stage = [&](int sbuf, int k0) {
        const uint32_t ob = (uint32_t)(sbuf * TSTG_W * 4);
        #pragma unroll
        for (int rr = 0; rr < 64; rr += 16) {
            cp16(dA + ob + (uint32_t)(rr*SSTR)*4, Ap + (long long)rr*KDIM + k0);
            cp16(dB + ob + (uint32_t)(rr*SSTR)*4, Wp + (long long)rr*KDIM + k0);
        }
    };

    constexpr int NK = KDIM / 32;
    load_stage(0, 0);  CP_COMMIT();
    load_stage(1, 32); CP_COMMIT();

    int sb = 0;
    for (int kt = 0; kt < NK; kt++) {
        CP_WAIT(1);
        __syncthreads();
        if (kt + 2 < NK) {
            int nb = sb + 2; if (nb >= 3) nb -= 3;
            load_stage(nb, (kt + 2) * 32);
        }
        CP_COMMIT();

        const uint32_t Au = Abase + (uint32_t)(sb*TSTG_W)*4;
        const uint32_t Bu = Bbase + (uint32_t)(sb*TSTG_W)*4;
        #pragma unroll
        for (int ks = 0; ks < 4; ks++) {
            const int kb = ks << 3;
            uint32_t af[2][4];
            uint32_t bq[2][4];
            #pragma unroll
            for (int mt = 0; mt < 2; mt++)
                ldsm4(af[mt], Au + (uint32_t)(a_off + mt*16*SSTR + kb)*4);
            #pragma unroll
            for (int p = 0; p < 2; p++)
                ldsm4(bq[p], Bu + (uint32_t)(b_off + p*16*SSTR + kb)*4);
            #pragma unroll
            for (int mt = 0; mt < 2; mt++) {
                #pragma unroll
                for (int p = 0; p < 2; p++) {
                    mma_tf32b(acc[mt][2*p  ], af[mt], bq[p][0], bq[p][1]);
                    mma_tf32b(acc[mt][2*p+1], af[mt], bq[p][2], bq[p][3]);
                }
            }
        }
        if (++sb == 3) sb = 0;
    }

    #pragma unroll
    for (int mt = 0; mt < 2; mt++) {
        #pragma unroll
        for (int nt = 0; nt < 4; nt++) {
            #pragma unroll
            for (int e = 0; e < 4; e++) {
                const int m = bm + wm + mt*16 + gid + ((e & 2) ? 8 : 0);
                const int n = bn + wn + nt*8 + tg*2 + (e & 1);
                float v = acc[mt][nt][e];
                if constexpr (MODE == MODE_QKV) {
                    const int b    = m >> 11;
                    const int ns   = m & 2047;
                    const int part = n / DIM_;
                    const int rem  = n - part*DIM_;
                    const int hh   = rem / HD_;
                    const int hd   = rem - hh*HD_;
                    if (part < 2) v += aux1[(b*N_ + ns)*HD_ + hd];
                    float* dst = (part == 0) ? g_Q : (part == 1 ? g_K : g_V);
                    dst[(((b << 3) + hh)*N_ + ns)*HD_ + hd] = v;
                } else if constexpr (MODE == MODE_PROJ) {
                    C[m*DIM_ + n] = v + aux1[n] + aux2[m*DIM_ + n];
                } else if constexpr (MODE == MODE_FINAL) {
                    const int np = npts[m >> 11];
                    C[m*DIM_ + n] = ((m & 2047) < np)
                                    ? (aux2[m*DIM_ + n] + v) : 0.0f;
                }
            }
        }
    }
}

// ---------------- fused GLU GEMM (64x64, BK=32, 2 stages, ldmatrix) (R16) ------
__global__ void __launch_bounds__(128, 4) gemm_glu_kernel(
    const float* __restrict__ A, const float* __restrict__ W1,
    const float* __restrict__ W3, float* __restrict__ C)
{
    extern __shared__ float gsm[];
    float* As = gsm;
    float* B1 = gsm + 2*TSTG_W;
    float* B3 = gsm + 4*TSTG_W;

    const int tid  = threadIdx.x;
    const int bm   = blockIdx.y << 6;
    const int bn   = blockIdx.x << 6;
    const int warp = tid >> 5;
    const int wm   = (warp & 1) * 32;
    const int wn   = (warp >> 1) * 32;
    const int lane = tid & 31;
    const int gid  = lane >> 2;
    const int tg   = lane & 3;
    const int r0   = tid >> 3;
    const int c0   = (tid & 7) << 2;

    const int a_off = (wm + ((lane>>3)&1)*8 + (lane&7))*SSTR + (lane>>4)*4;
    const int b_off = (wn + (lane>>4)*8 + (lane&7))*SSTR + ((lane>>3)&1)*4;

    float acc1[2][4][4], acc3[2][4][4];
    #pragma unroll
    for (int mt = 0; mt < 2; mt++)
        #pragma unroll
        for (int nt = 0; nt < 4; nt++)
            #pragma unroll
            for (int e = 0; e < 4; e++) { acc1[mt][nt][e] = 0.f; acc3[mt][nt][e] = 0.f; }

    const float* Ap  = A  + (long long)(bm + r0)*DIM_ + c0;
    const float* W1p = W1 + (long long)(bn + r0)*DIM_ + c0;
    const float* W3p = W3 + (long long)(bn + r0)*DIM_ + c0;
    const uint32_t dA = smem_u32(&As[r0*SSTR + c0]);
    const uint32_t d1 = smem_u32(&B1[r0*SSTR + c0]);
    const uint32_t d3 = smem_u32(&B3[r0*SSTR + c0]);
    const uint32_t Abase = smem_u32(As);
    const uint32_t B1base = smem_u32(B1);
    const uint32_t B3base = smem_u32(B3);

    auto load_stage = [&](int sbuf, int k0) {
        const uint32_t ob = (uint32_t)(sbuf * TSTG_W * 4);
        #pragma unroll
        for (int rr = 0; rr < 64; rr += 16) {
            cp16(dA + ob + (uint32_t)(rr*SSTR)*4, Ap  + (long long)rr*DIM_ + k0);
            cp16(d1 + ob + (uint32_t)(rr*SSTR)*4, W1p + (long long)rr*DIM_ + k0);
            cp16(d3 + ob + (uint32_t)(rr*SSTR)*4, W3p + (long long)rr*DIM_ + k0);
        }
    };

    constexpr int NK = DIM_ / 32;      // 12
    load_stage(0, 0);
    CP_COMMIT();

    int buf = 0;
    for (int kt = 0; kt < NK; kt++) {
        if (kt + 1 < NK) {
            load_stage(buf ^ 1, (kt + 1) * 32);
            CP_COMMIT();
            CP_WAIT(1);
        } else {
            CP_WAIT(0);
        }
        __syncthreads();

        const uint32_t Au  = Abase  + (uint32_t)(buf*TSTG_W)*4;
        const uint32_t B1u = B1base + (uint32_t)(buf*TSTG_W)*4;
        const uint32_t B3u = B3base + (uint32_t)(buf*TSTG_W)*4;
        #pragma unroll
        for (int ks = 0; ks < 4; ks++) {
            const int kb = ks << 3;
            uint32_t af[2][4];
            uint32_t q1[2][4], q3[2][4];
            #pragma unroll
            for (int mt = 0; mt < 2; mt++)
                ldsm4(af[mt], Au + (uint32_t)(a_off + mt*16*SSTR + kb)*4);
            #pragma unroll
            for (int p = 0; p < 2; p++) {
                ldsm4(q1[p], B1u + (uint32_t)(b_off + p*16*SSTR + kb)*4);
                ldsm4(q3[p], B3u + (uint32_t)(b_off + p*16*SSTR + kb)*4);
            }
            #pragma unroll
            for (int mt = 0; mt < 2; mt++) {
                #pragma unroll
                for (int p = 0; p < 2; p++) {
                    mma_tf32b(acc1[mt][2*p  ], af[mt], q1[p][0], q1[p][1]);
                    mma_tf32b(acc1[mt][2*p+1], af[mt], q1[p][2], q1[p][3]);
                    mma_tf32b(acc3[mt][2*p  ], af[mt], q3[p][0], q3[p][1]);
                    mma_tf32b(acc3[mt][2*p+1], af[mt], q3[p][2], q3[p][3]);
                }
            }
        }
        __syncthreads();
        buf ^= 1;
    }

    #pragma unroll
    for (int mt = 0; mt < 2; mt++) {
        #pragma unroll
        for (int nt = 0; nt < 4; nt++) {
            #pragma unroll
            for (int e = 0; e < 4; e++) {
                const int m = bm + wm + mt*16 + gid + ((e & 2) ? 8 : 0);
                const int n = bn + wn + nt*8 + tg*2 + (e & 1);
                const float v1 = acc1[mt][nt][e];
                const float v3 = acc3[mt][nt][e];
                C[m*HID_ + n] = (v1 / (1.0f + __expf(-v1))) * v3;
            }
        }
    }
}

// ---------------- flash attention with ldmatrix fragment feeds -----------------
#define AT_KSTR 52
#define AT_VSTR 56
#define AT_PSTR 68
#define AT_PSQ_W (64*AT_PSTR)
#define AT_K_W   (64*AT_KSTR)
#define AT_V_W   (64*AT_VSTR)
#define AT_SMEM_BYTES ((AT_PSQ_W + 2*AT_K_W + 2*AT_V_W) * 4)

__global__ void __launch_bounds__(128, 3) attn_tc_kernel(const float* __restrict__ mask) {
    extern __shared__ float sm[];
    float* PsQ = sm;
    float* Kd  = sm + AT_PSQ_W;
    float* Vd  = Kd + 2*AT_K_W;

    const int bh  = blockIdx.y;
    const int b   = bh >> 3;
    const int hh  = bh & 7;
    const int q0  = blockIdx.x * 64;
    const int tid = threadIdx.x;
    const int warp = tid >> 5;
    const int lane = tid & 31;
    const int gid  = lane >> 2;
    const int tg   = lane & 3;
    const int m0   = warp * 16;

    // ldmatrix lane-address pieces
    const int lrow8 = ((lane>>3)&1)*8 + (lane&7);   // A-frag row pattern
    const int lkhi  = (lane>>4)*4;                  // A-frag k-half
    const int brow  = (lane>>4)*8 + (lane&7);       // B-frag row pattern
    const int bkhi  = ((lane>>3)&1)*4;              // B-frag k-half

    const float* Qbase = g_Q + ((long long)bh*N_ + q0)*HD_;
    const uint32_t qdst = smem_u32(PsQ);
    for (int i = tid; i < 64*12; i += 128) {
        const int row = i / 12, c = i - row*12;
        cp16(qdst + (uint32_t)(row*AT_KSTR + c*4)*4, Qbase + row*HD_ + c*4);
    }
    CP_COMMIT();

    const float* Kbase = g_K + (long long)bh*N_*HD_;
    const float* Vbase = g_V + (long long)bh*N_*HD_;
    const uint32_t kdst = smem_u32(Kd);
    const uint32_t vdst = smem_u32(Vd);

    auto load_tile = [&](int bufi, int k0) {
        const uint32_t kb = kdst + (uint32_t)(bufi*AT_K_W)*4;
        const uint32_t vb = vdst + (uint32_t)(bufi*AT_V_W)*4;
        for (int i = tid; i < 64*12; i += 128) {
            const int row = i / 12, c = i - row*12;
            cp16(kb + (uint32_t)(row*AT_KSTR + c*4)*4, Kbase + (k0+row)*HD_ + c*4);
            cp16(vb + (uint32_t)(row*AT_VSTR + c*4)*4, Vbase + (k0+row)*HD_ + c*4);
        }
    };

    load_tile(0, 0);
    CP_COMMIT();

    CP_WAIT(1);
    __syncthreads();
    uint32_t qf[6][4];
    {
        const uint32_t Qu = smem_u32(PsQ);
        const int q_off = (m0 + lrow8)*AT_KSTR + lkhi;
        #pragma unroll
        for (int ks = 0; ks < 6; ks++)
            ldsm4(qf[ks], Qu + (uint32_t)(q_off + ks*8)*4);
    }
    __syncthreads();

    float oacc[6][4];
    #pragma unroll
    for (int nt = 0; nt < 6; nt++)
        #pragma unroll
        for (int e = 0; e < 4; e++) oacc[nt][e] = 0.f;
    float mr0 = -1e30f, mr1 = -1e30f, lr0 = 0.f, lr1 = 0.f;

    const float* Mr0 = mask + (long long)(b*N_ + q0 + m0 + gid)*N_;
    const float* Mr1 = Mr0 + 8LL*N_;
    const int k_off = brow*AT_KSTR + bkhi;           // K B-frag ldmatrix offset
    const int p_off = (m0 + lrow8)*AT_PSTR + lkhi;   // Ps A-frag ldmatrix offset

    int buf = 0;
    for (int kt = 0; kt < N_/64; kt++) {
        const int k0 = kt*64;
        if (kt + 1 < N_/64) {
            load_tile(buf ^ 1, k0 + 64);
            CP_COMMIT();
            CP_WAIT(1);
        } else {
            CP_WAIT(0);
        }
        __syncthreads();

        const uint32_t Ku = smem_u32(Kd) + (uint32_t)(buf*AT_K_W)*4;
        const float*  Vb = Vd + buf*AT_V_W;

        float2 mv0[8], mv1[8];
        #pragma unroll
        for (int nt = 0; nt < 8; nt++) {
            mv0[nt] = *(const float2*)(Mr0 + k0 + nt*8 + tg*2);
            mv1[nt] = *(const float2*)(Mr1 + k0 + nt*8 + tg*2);
        }

        // ---- S = Q . K^T  (K frags via ldmatrix x4: 16-row n-groups) ----
        float sacc[8][4];
        #pragma unroll
        for (int nt = 0; nt < 8; nt++)
            #pragma unroll
            for (int e = 0; e < 4; e++) sacc[nt][e] = 0.f;
        #pragma unroll
        for (int ks = 0; ks < 6; ks++) {
            const int kb = ks*8;
            #pragma unroll
            for (int g = 0; g < 4; g++) {
                uint32_t bq[4];
                ldsm4(bq, Ku + (uint32_t)(k_off + g*16*AT_KSTR + kb)*4);
                mma_tf32b(sacc[2*g  ], qf[ks], bq[0], bq[1]);
                mma_tf32b(sacc[2*g+1], qf[ks], bq[2], bq[3]);
            }
        }

        float mx0 = mr0, mx1 = mr1;
        #pragma unroll
        for (int nt = 0; nt < 8; nt++) {
            float v0 = sacc[nt][0]*SCALE_ + mv0[nt].x;
            float v1 = sacc[nt][1]*SCALE_ + mv0[nt].y;
            float v2 = sacc[nt][2]*SCALE_ + mv1[nt].x;
            float v3 = sacc[nt][3]*SCALE_ + mv1[nt].y;
            sacc[nt][0] = v0; sacc[nt][1] = v1; sacc[nt][2] = v2; sacc[nt][3] = v3;
            mx0 = fmaxf(mx0, fmaxf(v0, v1));
            mx1 = fmaxf(mx1, fmaxf(v2, v3));
        }
        mx0 = fmaxf(mx0, __shfl_xor_sync(0xffffffffu, mx0, 1));
        mx0 = fmaxf(mx0, __shfl_xor_sync(0xffffffffu, mx0, 2));
        mx1 = fmaxf(mx1, __shfl_xor_sync(0xffffffffu, mx1, 1));
        mx1 = fmaxf(mx1, __shfl_xor_sync(0xffffffffu, mx1, 2));
        const float a0 = __expf(mr0 - mx0);
        const float a1 = __expf(mr1 - mx1);
        mr0 = mx0; mr1 = mx1;
        lr0 *= a0;  lr1 *= a1;
        #pragma unroll
        for (int nt = 0; nt < 6; nt++) {
            oacc[nt][0] *= a0; oacc[nt][1] *= a0;
            oacc[nt][2] *= a1; oacc[nt][3] *= a1;
        }
        float ps0 = 0.f, ps1 = 0.f;
        #pragma unroll
        for (int nt = 0; nt < 8; nt++) {
            const int col = nt*8 + tg*2;
            float p0 = __expf(sacc[nt][0] - mx0);
            float p1 = __expf(sacc[nt][1] - mx0);
            float p2 = __expf(sacc[nt][2] - mx1);
            float p3 = __expf(sacc[nt][3] - mx1);
            ps0 += p0 + p1;
            ps1 += p2 + p3;
            PsQ[(m0+gid  )*AT_PSTR + col  ] = p0;
            PsQ[(m0+gid  )*AT_PSTR + col+1] = p1;
            PsQ[(m0+gid+8)*AT_PSTR + col  ] = p2;
            PsQ[(m0+gid+8)*AT_PSTR + col+1] = p3;
        }
        lr0 += ps0; lr1 += ps1;
        __syncwarp();

        // ---- O += P . V  (Ps A-frags via ldmatrix) ----
        const uint32_t Pu = smem_u32(PsQ);
        #pragma unroll
        for (int ks = 0; ks < 8; ks++) {
            const int kb = ks*8;
            uint32_t af[4];
            ldsm4(af, Pu + (uint32_t)(p_off + kb)*4);
            #pragma unroll
            for (int nt = 0; nt < 6; nt++) {
                uint32_t bv[2];
                bv[0] = __float_as_uint(Vb[(kb+tg  )*AT_VSTR + nt*8+gid]);
                bv[1] = __float_as_uint(Vb[(kb+tg+4)*AT_VSTR + nt*8+gid]);
                mma_tf32(oacc[nt], af, bv);
            }
        }
        __syncthreads();
        buf ^= 1;
    }

    lr0 += __shfl_xor_sync(0xffffffffu, lr0, 1);
    lr0 += __shfl_xor_sync(0xffffffffu, lr0, 2);
    lr1 += __shfl_xor_sync(0xffffffffu, lr1, 1);
    lr1 += __shfl_xor_sync(0xffffffffu, lr1, 2);
    const float i0 = 1.0f / lr0;
    const float i1 = 1.0f / lr1;

    const long long r0 = (long long)(b*N_ + q0 + m0 + gid)*DIM_ + hh*HD_;
    const long long r1 = r0 + 8LL*DIM_;
    #pragma unroll
    for (int nt = 0; nt < 6; nt++) {
        const int col = nt*8 + tg*2;
        *(float2*)&g_O[r0 + col] = make_float2(oacc[nt][0]*i0, oacc[nt][1]*i0);
        *(float2*)&g_O[r1 + col] = make_float2(oacc[nt][2]*i1, oacc[nt][3]*i1);
    }
}

// ---------------- launch ------------------------------------------------------
extern "C" void kernel_launch(void* const* d_in, const int* in_sizes, int n_in,
                              void* d_out, int out_size)
{
    const float* x       = (const float*)d_in[0];
    const float* pos     = (const float*)d_in[1];
    const float* mask    = (const float*)d_in[2];
    const int*   npts    = (const int*)d_in[3];   // int32 (jax canonicalized)
    const float* norm1_w = (const float*)d_in[4];
    const float* norm2_w = (const float*)d_in[5];
    const float* w_qkv   = (const float*)d_in[6];
    const float* w_proj  = (const float*)d_in[7];
    const float* b_proj  = (const float*)d_in[8];
    const float* w1      = (const float*)d_in[9];
    const float* w2      = (const float*)d_in[10];
    const float* w3      = (const float*)d_in[11];
    float* out = (float*)d_out;

    float *xa, *O, *h, *hf, *gb;
    cudaGetSymbolAddress((void**)&xa, g_xa);
    cudaGetSymbolAddress((void**)&O,  g_O);
    cudaGetSymbolAddress((void**)&h,  g_h);
    cudaGetSymbolAddress((void**)&hf, g_hf);
    cudaGetSymbolAddress((void**)&gb, g_gb);

    cudaFuncSetAttribute(attn_tc_kernel,
                         cudaFuncAttributeMaxDynamicSharedMemorySize, AT_SMEM_BYTES);
    cudaFuncSetAttribute(gemm_glu_kernel,
                         cudaFuncAttributeMaxDynamicSharedMemorySize, GLU_SMEM_BYTES);
    cudaFuncSetAttribute(gemm_tc_kernel<DIM_, MODE_QKV>,
                         cudaFuncAttributeMaxDynamicSharedMemorySize, GEMM_SMEM_BYTES);
    cudaFuncSetAttribute(gemm_tc_kernel<DIM_, MODE_PROJ>,
                         cudaFuncAttributeMaxDynamicSharedMemorySize, GEMM_SMEM_BYTES);
    cudaFuncSetAttribute(gemm_tc_kernel<HID_, MODE_FINAL>,
                         cudaFuncAttributeMaxDynamicSharedMemorySize, GEMM_SMEM_BYTES);

    // 1) xa = rmsnorm(x) * norm1_w
    rmsnorm_kernel<<<M_, 128>>>(x, norm1_w, xa);

    // 2) qkv GEMM + pos add + split into Q/K/V [B,H,N,HD]
    gemm_tc_kernel<DIM_, MODE_QKV><<<dim3(3*DIM_/64, M_/64), 128, GEMM_SMEM_BYTES>>>(
        xa, w_qkv, nullptr, pos, nullptr, nullptr);

    // 3) attention -> g_O [B,N,H*HD]
    attn_tc_kernel<<<dim3(N_/64, B_*H_), 128, AT_SMEM_BYTES>>>(mask);

    // 4) h = x + O @ w_proj^T + b_proj
    gemm_tc_kernel<DIM_, MODE_PROJ><<<dim3(DIM_/64, M_/64), 128, GEMM_SMEM_BYTES>>>(
        O, w_proj, h, b_proj, x, nullptr);

    // 5) hf = rmsnorm(h) * norm2_w
    rmsnorm_kernel<<<M_, 128>>>(h, norm2_w, hf);

    // 6+7) g = silu(hf @ w1^T) * (hf @ w3^T)   (fused GLU)
    gemm_glu_kernel<<<dim3(HID_/64, M_/64), 128, GLU_SMEM_BYTES>>>(
        hf, w1, w3, gb);

    // 8) out = keep ? h + g @ w2^T : 0
    gemm_tc_kernel<HID_, MODE_FINAL><<<dim3(DIM_/64, M_/64), 128, GEMM_SMEM_BYTES>>>(
        gb, w2, out, nullptr, h, npts);
}